// round 2
// baseline (speedup 1.0000x reference)
#include <cuda_runtime.h>
#include <cuda_bf16.h>
#include <math.h>

#define Bsz 1024
#define TT  730
#define INN 64
#define HH  512
#define KK  (INN + HH)   // 576
#define G4  (4 * HH)     // 2048

#define BM 64
#define BH 64
#define BK 16

// Scratch (allocation-free: device globals)
__device__ float g_Wc[KK * G4];        // [K][4H] transposed combined weights (4.5 MB)
__device__ float g_h[2][Bsz * HH];     // ping-pong hidden state (4 MB)
__device__ float g_c[Bsz * HH];        // cell state (2 MB)

// Build Wc[k][g*H + h] = k < IN ? W_ih[g*H+h][k] : W_hh[g*H+h][k-IN]
__global__ void prep_kernel(const float* __restrict__ Wih,
                            const float* __restrict__ Whh) {
    int idx = blockIdx.x * blockDim.x + threadIdx.x;
    if (idx >= KK * G4) return;
    int k   = idx / G4;
    int col = idx % G4;
    g_Wc[idx] = (k < INN) ? Wih[(size_t)col * INN + k]
                          : Whh[(size_t)col * HH + (k - INN)];
}

__global__ void zero_kernel() {
    int idx = blockIdx.x * blockDim.x + threadIdx.x;
    if (idx < Bsz * HH) {
        g_h[0][idx] = 0.0f;
        g_c[idx]    = 0.0f;
    }
}

__device__ __forceinline__ float sigmoidf_(float x) {
    return 1.0f / (1.0f + __expf(-x));
}

// One LSTM timestep: z = [x_t | h_prev] @ Wc + b ; gate math ; write h_new, c.
// CTA tile: BM=64 batches x BH=64 h-units x 4 gates. 256 threads, 4x4x4 accs.
__global__ __launch_bounds__(256, 1)
void step_kernel(const float* __restrict__ xd,
                 const float* __restrict__ bias,
                 int t, int sel) {
    const float* __restrict__ hprev = g_h[sel];
    float* __restrict__ hnew = g_h[sel ^ 1];

    const int h0 = blockIdx.x * BH;   // 0..7  -> h tile
    const int b0 = blockIdx.y * BM;   // 0..15 -> batch tile

    __shared__ float As[BK][BM + 4];      // [k][m], stride 68 (16B-aligned rows)
    __shared__ float Ws[4][BK][BH];       // [gate][k][n]

    const int tid = threadIdx.x;
    const int tx  = tid & 15;   // n direction (h)
    const int ty  = tid >> 4;   // m direction (b)

    float acc[4][4][4];
#pragma unroll
    for (int g = 0; g < 4; g++)
#pragma unroll
        for (int i = 0; i < 4; i++)
#pragma unroll
            for (int j = 0; j < 4; j++) acc[g][i][j] = 0.0f;

    for (int kc = 0; kc < KK; kc += BK) {
        // Load A tile: 64 m x 16 k
#pragma unroll
        for (int r = 0; r < 4; r++) {
            int lin = tid + r * 256;      // 0..1023
            int m   = lin >> 4;
            int kk  = lin & 15;
            int k   = kc + kk;
            int b   = b0 + m;
            float v;
            if (k < INN)
                v = xd[(size_t)b * TT * INN + (size_t)t * INN + k];
            else
                v = hprev[b * HH + (k - INN)];
            As[kk][m] = v;
        }
        // Load W tiles: 4 gates x 16 k x 64 n
#pragma unroll
        for (int r = 0; r < 16; r++) {
            int lin = tid + r * 256;      // 0..4095
            int g   = lin >> 10;
            int rem = lin & 1023;
            int kk  = rem >> 6;
            int n   = rem & 63;
            Ws[g][kk][n] = g_Wc[(size_t)(kc + kk) * G4 + g * HH + h0 + n];
        }
        __syncthreads();

#pragma unroll
        for (int kk = 0; kk < BK; kk++) {
            float4 a4 = *(const float4*)&As[kk][ty * 4];
            float a[4] = {a4.x, a4.y, a4.z, a4.w};
            float w[4][4];
#pragma unroll
            for (int g = 0; g < 4; g++) {
                float4 w4 = *(const float4*)&Ws[g][kk][tx * 4];
                w[g][0] = w4.x; w[g][1] = w4.y; w[g][2] = w4.z; w[g][3] = w4.w;
            }
#pragma unroll
            for (int g = 0; g < 4; g++)
#pragma unroll
                for (int i = 0; i < 4; i++)
#pragma unroll
                    for (int j = 0; j < 4; j++)
                        acc[g][i][j] = fmaf(a[i], w[g][j], acc[g][i][j]);
        }
        __syncthreads();
    }

    // Epilogue: gates + state update
#pragma unroll
    for (int i = 0; i < 4; i++) {
        int b = b0 + ty * 4 + i;
#pragma unroll
        for (int j = 0; j < 4; j++) {
            int h = h0 + tx * 4 + j;
            float zi = acc[0][i][j] + bias[0 * HH + h];
            float zf = acc[1][i][j] + bias[1 * HH + h];
            float zg = acc[2][i][j] + bias[2 * HH + h];
            float zo = acc[3][i][j] + bias[3 * HH + h];
            float ig = sigmoidf_(zi);
            float fg = sigmoidf_(zf);
            float gg = tanhf(zg);
            float og = sigmoidf_(zo);
            int idx  = b * HH + h;
            float c  = fg * g_c[idx] + ig * gg;
            g_c[idx] = c;
            hnew[idx] = og * tanhf(c);
        }
    }
}

// out[b] = relu(dot(h_T[b,:], Wl) + bl)
__global__ void head_kernel(const float* __restrict__ Wl,
                            const float* __restrict__ bl,
                            float* __restrict__ out, int sel) {
    int b = blockIdx.x;
    const float* __restrict__ h = g_h[sel] + (size_t)b * HH;
    float s = 0.0f;
    for (int i = threadIdx.x; i < HH; i += blockDim.x)
        s += h[i] * Wl[i];
#pragma unroll
    for (int o = 16; o; o >>= 1) s += __shfl_down_sync(0xffffffffu, s, o);
    __shared__ float red[8];
    if ((threadIdx.x & 31) == 0) red[threadIdx.x >> 5] = s;
    __syncthreads();
    if (threadIdx.x < 32) {
        s = (threadIdx.x < (blockDim.x >> 5)) ? red[threadIdx.x] : 0.0f;
#pragma unroll
        for (int o = 4; o; o >>= 1) s += __shfl_down_sync(0xffffffffu, s, o);
        if (threadIdx.x == 0) out[b] = fmaxf(s + bl[0], 0.0f);
    }
}

extern "C" void kernel_launch(void* const* d_in, const int* in_sizes, int n_in,
                              void* d_out, int out_size) {
    const float* xd   = (const float*)d_in[0];
    const float* Wih  = (const float*)d_in[1];
    const float* Whh  = (const float*)d_in[2];
    const float* bias = (const float*)d_in[3];
    const float* Wl   = (const float*)d_in[4];
    const float* bl   = (const float*)d_in[5];
    float* out = (float*)d_out;

    prep_kernel<<<(KK * G4 + 255) / 256, 256>>>(Wih, Whh);
    zero_kernel<<<(Bsz * HH + 255) / 256, 256>>>();

    for (int t = 0; t < TT; t++) {
        step_kernel<<<dim3(HH / BH, Bsz / BM), 256>>>(xd, bias, t, t & 1);
    }
    // Final h lives in g_h[(729 & 1) ^ 1] = g_h[0]
    head_kernel<<<Bsz, 256>>>(Wl, bl, out, 0);
}

// round 3
// speedup vs baseline: 3.0530x; 3.0530x over previous
#include <cuda_runtime.h>
#include <math.h>

#define Bsz 1024
#define TT  730
#define INN 64
#define HH  512
#define KK  (INN + HH)   // 576
#define G4  (4 * HH)     // 2048

#define BM 128
#define BN 128
#define BK 32
#define NCHUNK (KK / BK)   // 18

#define AS_STRIDE 36       // 128 x 36 floats, conflict-free A fragment loads
#define BS_STRIDE 136      // 32 x 136 floats, conflict-free B fragment loads
#define ZS_STRIDE 132
#define A_BUF (BM * AS_STRIDE)          // 4608 floats
#define B_BUF (BK * BS_STRIDE)          // 4352 floats
#define SMEM_FLOATS (2 * A_BUF + 2 * B_BUF)   // 17920 floats = 71680 B
#define SMEM_BYTES (SMEM_FLOATS * 4)

// Device-global scratch (allocation-free)
__device__ float g_Wc[KK * G4];     // [k][h*4+g], tf32-rounded, gate-interleaved
__device__ float g_bperm[G4];       // bias permuted to h*4+g
__device__ float g_h[2][Bsz * HH];  // ping-pong hidden state (fp32)
__device__ float g_c[Bsz * HH];     // cell state (fp32)

__device__ __forceinline__ float to_tf32(float v) {
    unsigned u;
    asm("cvt.rna.tf32.f32 %0, %1;" : "=r"(u) : "f"(v));
    return __uint_as_float(u);
}

__device__ __forceinline__ void cpa16(float* dst, const float* src) {
    unsigned d = (unsigned)__cvta_generic_to_shared(dst);
    asm volatile("cp.async.cg.shared.global [%0], [%1], 16;\n" :: "r"(d), "l"(src));
}

#define CP_COMMIT() asm volatile("cp.async.commit_group;\n")
#define CP_WAIT0()  asm volatile("cp.async.wait_group 0;\n" ::: "memory")

#define MMA_TF32(d, a, b)                                                     \
    asm volatile(                                                             \
        "mma.sync.aligned.m16n8k8.row.col.f32.tf32.tf32.f32 "                 \
        "{%0,%1,%2,%3}, {%4,%5,%6,%7}, {%8,%9}, {%0,%1,%2,%3};"               \
        : "+f"((d)[0]), "+f"((d)[1]), "+f"((d)[2]), "+f"((d)[3])              \
        : "r"((a)[0]), "r"((a)[1]), "r"((a)[2]), "r"((a)[3]),                 \
          "r"((b)[0]), "r"((b)[1]))

// Build gate-interleaved tf32 weights + permuted bias
__global__ void prep_kernel(const float* __restrict__ Wih,
                            const float* __restrict__ Whh,
                            const float* __restrict__ bias) {
    int idx = blockIdx.x * blockDim.x + threadIdx.x;
    if (idx >= KK * G4) return;
    int k    = idx / G4;
    int colp = idx % G4;
    int h    = colp >> 2;
    int g    = colp & 3;
    float v = (k < INN) ? Wih[(size_t)(g * HH + h) * INN + k]
                        : Whh[(size_t)(g * HH + h) * HH + (k - INN)];
    g_Wc[idx] = to_tf32(v);
    if (idx < G4) g_bperm[idx] = bias[g * HH + h];   // same (h,g) decode
}

__global__ void zero_kernel() {
    int idx = blockIdx.x * blockDim.x + threadIdx.x;
    if (idx < Bsz * HH) {
        g_h[0][idx] = 0.0f;
        g_c[idx]    = 0.0f;
    }
}

__device__ __forceinline__ float sigf(float x) {
    return __fdividef(1.0f, 1.0f + __expf(-x));
}
__device__ __forceinline__ float tanhfast(float x) {
    // tanh(x) = 2*sigmoid(2x) - 1
    return fmaf(2.0f, sigf(2.0f * x), -1.0f);
}

// One LSTM timestep, fused GEMM (tf32 tensor cores) + gate epilogue.
__global__ __launch_bounds__(256, 1)
void step_kernel(const float* __restrict__ xd, int t, int sel) {
    extern __shared__ float smem[];
    float* As = smem;                 // 2 x A_BUF
    float* Bs = smem + 2 * A_BUF;     // 2 x B_BUF
    float* Zs = smem;                 // reused after mainloop (128 x 132)

    const float* __restrict__ hprev = g_h[sel];
    float* __restrict__ hnew = g_h[sel ^ 1];

    const int tid  = threadIdx.x;
    const int lane = tid & 31;
    const int wid  = tid >> 5;
    const int grp  = lane >> 2;   // groupID
    const int tig  = lane & 3;    // thread in group
    const int wm   = wid & 1;     // warp m: 0..1 (64 rows each)
    const int wn   = wid >> 1;    // warp n: 0..3 (32 cols each)

    const int n0 = blockIdx.x * BN;   // 0..15 tiles over 2048 interleaved cols
    const int b0 = blockIdx.y * BM;   // 0..7 tiles over 1024 batches

    float acc[4][4][4];
#pragma unroll
    for (int mf = 0; mf < 4; mf++)
#pragma unroll
        for (int nf = 0; nf < 4; nf++)
#pragma unroll
            for (int r = 0; r < 4; r++) acc[mf][nf][r] = 0.0f;

    // ---- prologue: issue chunk 0 ----
#pragma unroll
    for (int i = 0; i < 4; i++) {
        int lin = i * 256 + tid;
        int row = lin >> 3, kq = lin & 7;
        const float* src = xd + ((size_t)(b0 + row) * TT + t) * INN + kq * 4;
        cpa16(&As[row * AS_STRIDE + kq * 4], src);
    }
#pragma unroll
    for (int i = 0; i < 4; i++) {
        int lin = i * 256 + tid;
        int kr = lin >> 5, nq = lin & 31;
        cpa16(&Bs[kr * BS_STRIDE + nq * 4], g_Wc + (size_t)kr * G4 + n0 + nq * 4);
    }
    CP_COMMIT();

    int buf = 0;
#pragma unroll 1
    for (int kc = 0; kc < NCHUNK; kc++) {
        CP_WAIT0();
        __syncthreads();

        if (kc + 1 < NCHUNK) {
            int nb = buf ^ 1;
            int kbase = (kc + 1) * BK;
#pragma unroll
            for (int i = 0; i < 4; i++) {
                int lin = i * 256 + tid;
                int row = lin >> 3, kq = lin & 7;
                const float* src;
                if (kbase < INN)
                    src = xd + ((size_t)(b0 + row) * TT + t) * INN + kbase + kq * 4;
                else
                    src = hprev + (size_t)(b0 + row) * HH + (kbase - INN) + kq * 4;
                cpa16(&As[nb * A_BUF + row * AS_STRIDE + kq * 4], src);
            }
#pragma unroll
            for (int i = 0; i < 4; i++) {
                int lin = i * 256 + tid;
                int kr = lin >> 5, nq = lin & 31;
                cpa16(&Bs[nb * B_BUF + kr * BS_STRIDE + nq * 4],
                      g_Wc + (size_t)(kbase + kr) * G4 + n0 + nq * 4);
            }
            CP_COMMIT();
        }

        const float* Ab = &As[buf * A_BUF];
        const float* Bb = &Bs[buf * B_BUF];
#pragma unroll
        for (int ks = 0; ks < 4; ks++) {
            const int kb = ks * 8;
            unsigned a[4][4], b[4][2];
#pragma unroll
            for (int mf = 0; mf < 4; mf++) {
                const float* ap = Ab + (wm * 64 + mf * 16 + grp) * AS_STRIDE + kb + tig;
                a[mf][0] = __float_as_uint(ap[0]);
                a[mf][1] = __float_as_uint(ap[8 * AS_STRIDE]);
                a[mf][2] = __float_as_uint(ap[4]);
                a[mf][3] = __float_as_uint(ap[8 * AS_STRIDE + 4]);
            }
#pragma unroll
            for (int nf = 0; nf < 4; nf++) {
                const float* bp = Bb + (kb + tig) * BS_STRIDE + wn * 32 + nf * 8 + grp;
                b[nf][0] = __float_as_uint(bp[0]);
                b[nf][1] = __float_as_uint(bp[4 * BS_STRIDE]);
            }
#pragma unroll
            for (int mf = 0; mf < 4; mf++)
#pragma unroll
                for (int nf = 0; nf < 4; nf++)
                    MMA_TF32(acc[mf][nf], a[mf], b[nf]);
        }
        buf ^= 1;
    }

    // ---- epilogue: z -> smem (gate quads contiguous), then gate math ----
    __syncthreads();
#pragma unroll
    for (int mf = 0; mf < 4; mf++) {
        int row = wm * 64 + mf * 16 + grp;
#pragma unroll
        for (int nf = 0; nf < 4; nf++) {
            int col = wn * 32 + nf * 8 + tig * 2;
            *(float2*)&Zs[row * ZS_STRIDE + col] =
                make_float2(acc[mf][nf][0], acc[mf][nf][1]);
            *(float2*)&Zs[(row + 8) * ZS_STRIDE + col] =
                make_float2(acc[mf][nf][2], acc[mf][nf][3]);
        }
    }
    __syncthreads();

    const int hq = tid & 7;              // which float4 of the 32-h block
    const int hb = blockIdx.x * 32;      // global h base for this CTA
    float4 bq[4];
#pragma unroll
    for (int u = 0; u < 4; u++)
        bq[u] = *(const float4*)&g_bperm[n0 + (hq * 4 + u) * 4];

#pragma unroll
    for (int p = 0; p < 4; p++) {
        int bl = p * 32 + (tid >> 3);
        size_t cidx = (size_t)(b0 + bl) * HH + hb + hq * 4;
        float4 cv = *(float4*)&g_c[cidx];
        float cin[4] = {cv.x, cv.y, cv.z, cv.w};
        float cc[4], hh[4];
#pragma unroll
        for (int u = 0; u < 4; u++) {
            float4 z = *(float4*)&Zs[bl * ZS_STRIDE + (hq * 4 + u) * 4];
            float zi = z.x + bq[u].x;
            float zf = z.y + bq[u].y;
            float zg = z.z + bq[u].z;
            float zo = z.w + bq[u].w;
            float ig = sigf(zi);
            float fg = sigf(zf);
            float gg = tanhfast(zg);
            float og = sigf(zo);
            float cn = fmaf(fg, cin[u], ig * gg);
            cc[u] = cn;
            hh[u] = og * tanhfast(cn);
        }
        *(float4*)&g_c[cidx]  = make_float4(cc[0], cc[1], cc[2], cc[3]);
        *(float4*)&hnew[cidx] = make_float4(hh[0], hh[1], hh[2], hh[3]);
    }
}

// out[b] = relu(dot(h_T[b,:], Wl) + bl)
__global__ void head_kernel(const float* __restrict__ Wl,
                            const float* __restrict__ bl,
                            float* __restrict__ out, int sel) {
    int b = blockIdx.x;
    const float* __restrict__ h = g_h[sel] + (size_t)b * HH;
    float s = 0.0f;
    for (int i = threadIdx.x; i < HH; i += blockDim.x)
        s += h[i] * Wl[i];
#pragma unroll
    for (int o = 16; o; o >>= 1) s += __shfl_down_sync(0xffffffffu, s, o);
    __shared__ float red[8];
    if ((threadIdx.x & 31) == 0) red[threadIdx.x >> 5] = s;
    __syncthreads();
    if (threadIdx.x < 32) {
        s = (threadIdx.x < (blockDim.x >> 5)) ? red[threadIdx.x] : 0.0f;
#pragma unroll
        for (int o = 4; o; o >>= 1) s += __shfl_down_sync(0xffffffffu, s, o);
        if (threadIdx.x == 0) out[b] = fmaxf(s + bl[0], 0.0f);
    }
}

extern "C" void kernel_launch(void* const* d_in, const int* in_sizes, int n_in,
                              void* d_out, int out_size) {
    const float* xd   = (const float*)d_in[0];
    const float* Wih  = (const float*)d_in[1];
    const float* Whh  = (const float*)d_in[2];
    const float* bias = (const float*)d_in[3];
    const float* Wl   = (const float*)d_in[4];
    const float* bl   = (const float*)d_in[5];
    float* out = (float*)d_out;

    cudaFuncSetAttribute(step_kernel,
                         cudaFuncAttributeMaxDynamicSharedMemorySize, SMEM_BYTES);

    prep_kernel<<<(KK * G4 + 255) / 256, 256>>>(Wih, Whh, bias);
    zero_kernel<<<(Bsz * HH + 255) / 256, 256>>>();

    for (int t = 0; t < TT; t++) {
        step_kernel<<<dim3(G4 / BN, Bsz / BM), 256, SMEM_BYTES>>>(xd, t, t & 1);
    }
    // Final h lives in g_h[0] (t=729 odd writes sel^1 = 0)
    head_kernel<<<Bsz, 256>>>(Wl, bl, out, 0);
}

// round 5
// speedup vs baseline: 3.1202x; 1.0220x over previous
#include <cuda_runtime.h>
#include <math.h>
#include <stdint.h>

#define Bsz 1024
#define TT  730
#define INN 64
#define HH  512
#define KK  576
#define G4  2048

#define BM 128
#define BN 128
#define BK 32
#define NCHUNK 18
#define NSTAGE 3

#define STRIDE 40                          // smem row stride in floats (conflict-free LDS.64)
#define TILE_FLOATS (128 * STRIDE)         // 5120 floats per operand tile
#define STAGE_FLOATS (2 * TILE_FLOATS)     // A + B
#define SMEM_FLOATS (NSTAGE * STAGE_FLOATS)
#define SMEM_BYTES  (SMEM_FLOATS * 4)      // 122880 B
#define ZS_STRIDE 132

// Device-global scratch (allocation-free)
__device__ float g_Wc[(size_t)G4 * KK];   // [colp][kperm], tf32-rounded, gate-interleaved cols
__device__ float g_bperm[G4];             // bias permuted to h*4+g
__device__ float g_h[2][Bsz * HH];        // hidden state, k-PERMUTED layout within 8-blocks
__device__ float g_c[Bsz * HH];           // cell state, natural layout

__device__ __forceinline__ float to_tf32(float v) {
    unsigned u;
    asm("cvt.rna.tf32.f32 %0, %1;" : "=r"(u) : "f"(v));
    return __uint_as_float(u);
}
__device__ __forceinline__ void cpa16(float* dst, const float* src) {
    unsigned d = (unsigned)__cvta_generic_to_shared(dst);
    asm volatile("cp.async.cg.shared.global [%0], [%1], 16;" :: "r"(d), "l"(src));
}
#define CP_COMMIT() asm volatile("cp.async.commit_group;")
#define CP_WAIT(n)  asm volatile("cp.async.wait_group %0;" :: "n"(n) : "memory")

#define MMA_TF32(d, a, b)                                                     \
    asm volatile(                                                             \
        "mma.sync.aligned.m16n8k8.row.col.f32.tf32.tf32.f32 "                 \
        "{%0,%1,%2,%3}, {%4,%5,%6,%7}, {%8,%9}, {%0,%1,%2,%3};"               \
        : "+f"((d)[0]), "+f"((d)[1]), "+f"((d)[2]), "+f"((d)[3])              \
        : "r"((a)[0]), "r"((a)[1]), "r"((a)[2]), "r"((a)[3]),                 \
          "r"((b)[0]), "r"((b)[1]))

// perm within each 8-block: pos(k) = (k&~7) | ((k&3)*2 + ((k>>2)&1))
// inverse: k(pos)          = (pos&~7) | ((pos&1)*4 + ((pos>>1)&3))
__device__ __forceinline__ int kinv(int pos) {
    return (pos & ~7) | ((pos & 1) << 2) | ((pos >> 1) & 3);
}

// Build gate-interleaved, k-permuted tf32 weights + permuted bias
__global__ void prep_kernel(const float* __restrict__ Wih,
                            const float* __restrict__ Whh,
                            const float* __restrict__ bias) {
    int idx = blockIdx.x * blockDim.x + threadIdx.x;
    if (idx >= G4 * KK) return;
    int colp = idx / KK;
    int kpos = idx % KK;
    int k = kinv(kpos);
    int h = colp >> 2, g = colp & 3;
    float v = (k < INN) ? Wih[(size_t)(g * HH + h) * INN + k]
                        : Whh[(size_t)(g * HH + h) * HH + (k - INN)];
    g_Wc[idx] = to_tf32(v);
    if (idx < G4) g_bperm[idx] = bias[(idx & 3) * HH + (idx >> 2)];
}

__global__ void zero_kernel() {
    int idx = blockIdx.x * blockDim.x + threadIdx.x;
    if (idx < Bsz * HH) { g_h[0][idx] = 0.0f; g_c[idx] = 0.0f; }
}

__device__ __forceinline__ float sigf(float x) {
    return __fdividef(1.0f, 1.0f + __expf(-x));
}
__device__ __forceinline__ float tanhfast(float x) {
    return fmaf(2.0f, sigf(2.0f * x), -1.0f);
}

__global__ __launch_bounds__(256, 1)
void step_kernel(const float* __restrict__ xd, int t, int sel) {
    extern __shared__ float smem[];
    float* Zs = smem;   // epilogue reuse (128 x 132 floats)

    const float* __restrict__ hprev = g_h[sel];
    float* __restrict__ hnew = g_h[sel ^ 1];

    const int tid  = threadIdx.x;
    const int lane = tid & 31;
    const int wid  = tid >> 5;
    const int grp  = lane >> 2;
    const int tig  = lane & 3;
    const int wm   = wid & 1;     // 2 warps over M (64 rows each)
    const int wn   = wid >> 1;    // 4 warps over N (32 cols each)

    const int nt = blockIdx.x, mt = blockIdx.y;
    const int n0 = nt * BN, b0 = mt * BM;

    float acc[4][4][4];
#pragma unroll
    for (int mf = 0; mf < 4; mf++)
#pragma unroll
        for (int nf = 0; nf < 4; nf++)
#pragma unroll
            for (int r = 0; r < 4; r++) acc[mf][nf][r] = 0.0f;

    // producer: load chunk kc into stage kc % NSTAGE
    auto load_chunk = [&](int kc) {
        const int s = kc % NSTAGE;
        float* Ab = smem + s * STAGE_FLOATS;
        float* Bb = Ab + TILE_FLOATS;
        if (kc < 2) {
            // x chunk: LDG + on-the-fly k-perm + STS
            int r = tid >> 1, half = tid & 1;
            const float* src = xd + ((size_t)(b0 + r) * TT + t) * INN + kc * 32 + half * 16;
            float* dst = Ab + r * STRIDE;
#pragma unroll
            for (int q = 0; q < 4; q++) {
                float4 v = *(const float4*)(src + q * 4);
                int j0 = half * 16 + q * 4;       // j0..j0+3
                // pos(j) = (j&24) | ((j&3)*2 + ((j>>2)&1))
                int blk = j0 & 24, sub = (j0 >> 2) & 1;
                dst[blk + 0 + sub] = v.x;
                dst[blk + 2 + sub] = v.y;
                dst[blk + 4 + sub] = v.z;
                dst[blk + 6 + sub] = v.w;
            }
        } else {
            // h chunk: already permuted in gmem, straight cp.async
#pragma unroll
            for (int i = 0; i < 4; i++) {
                int u = i * 256 + tid;
                int r = u >> 3, q = u & 7;
                cpa16(Ab + r * STRIDE + q * 4,
                      hprev + (size_t)(b0 + r) * HH + (kc - 2) * 32 + q * 4);
            }
        }
        // B tile: pre-permuted weights, straight cp.async
#pragma unroll
        for (int i = 0; i < 4; i++) {
            int u = i * 256 + tid;
            int r = u >> 3, q = u & 7;
            cpa16(Bb + r * STRIDE + q * 4,
                  g_Wc + (size_t)(n0 + r) * KK + kc * 32 + q * 4);
        }
        CP_COMMIT();
    };

    load_chunk(0);
    load_chunk(1);

#pragma unroll 1
    for (int kc = 0; kc < NCHUNK; kc++) {
        if (kc == NCHUNK - 1) CP_WAIT(0); else CP_WAIT(1);
        __syncthreads();

        if (kc + 2 < NCHUNK) load_chunk(kc + 2);

        const float* Ab = smem + (kc % NSTAGE) * STAGE_FLOATS;
        const float* Bb = Ab + TILE_FLOATS;
#pragma unroll
        for (int ks = 0; ks < 4; ks++) {
            const int kb = ks * 8;
            unsigned a[4][4], b[4][2];
#pragma unroll
            for (int mf = 0; mf < 4; mf++) {
                int r0 = wm * 64 + mf * 16 + grp;
                float2 lo = *(const float2*)&Ab[r0 * STRIDE + kb + tig * 2];
                float2 hi = *(const float2*)&Ab[(r0 + 8) * STRIDE + kb + tig * 2];
                a[mf][0] = __float_as_uint(lo.x);
                a[mf][1] = __float_as_uint(hi.x);
                a[mf][2] = __float_as_uint(lo.y);
                a[mf][3] = __float_as_uint(hi.y);
            }
#pragma unroll
            for (int nf = 0; nf < 4; nf++) {
                int col = wn * 32 + nf * 8 + grp;
                float2 bv = *(const float2*)&Bb[col * STRIDE + kb + tig * 2];
                b[nf][0] = __float_as_uint(bv.x);
                b[nf][1] = __float_as_uint(bv.y);
            }
#pragma unroll
            for (int mf = 0; mf < 4; mf++)
#pragma unroll
                for (int nf = 0; nf < 4; nf++)
                    MMA_TF32(acc[mf][nf], a[mf], b[nf]);
        }
    }

    // ---- epilogue: z -> smem (gate quads contiguous), then gate math ----
    __syncthreads();
#pragma unroll
    for (int mf = 0; mf < 4; mf++) {
        int row = wm * 64 + mf * 16 + grp;
#pragma unroll
        for (int nf = 0; nf < 4; nf++) {
            int col = wn * 32 + nf * 8 + tig * 2;
            *(float2*)&Zs[row * ZS_STRIDE + col] =
                make_float2(acc[mf][nf][0], acc[mf][nf][1]);
            *(float2*)&Zs[(row + 8) * ZS_STRIDE + col] =
                make_float2(acc[mf][nf][2], acc[mf][nf][3]);
        }
    }
    __syncthreads();

    const int hq = tid & 7;            // which h-quad (4 h-units) of the 32-h block
    const int hb = nt * 32;            // global h base for this CTA
    float4 bq[4];
#pragma unroll
    for (int u = 0; u < 4; u++)
        bq[u] = *(const float4*)&g_bperm[n0 + (hq * 4 + u) * 4];

    // permuted h-store base: within 8-block (hq>>1), positions (hq&1) + 2*u
    const int hpb = hb + ((hq >> 1) << 3) + (hq & 1);

#pragma unroll
    for (int p = 0; p < 4; p++) {
        int bl = p * 32 + (tid >> 3);
        size_t rowb = (size_t)(b0 + bl) * HH;
        size_t cidx = rowb + hb + hq * 4;
        float4 cv = *(float4*)&g_c[cidx];
        float cin[4] = {cv.x, cv.y, cv.z, cv.w};
        float cc[4], hh[4];
#pragma unroll
        for (int u = 0; u < 4; u++) {
            float4 z = *(float4*)&Zs[bl * ZS_STRIDE + (hq * 4 + u) * 4];
            float zi = z.x + bq[u].x;
            float zf = z.y + bq[u].y;
            float zg = z.z + bq[u].z;
            float zo = z.w + bq[u].w;
            float ig = sigf(zi), fg = sigf(zf);
            float gg = tanhfast(zg), og = sigf(zo);
            float cn = fmaf(fg, cin[u], ig * gg);
            cc[u] = cn;
            hh[u] = og * tanhfast(cn);
        }
        *(float4*)&g_c[cidx] = make_float4(cc[0], cc[1], cc[2], cc[3]);
#pragma unroll
        for (int u = 0; u < 4; u++)
            hnew[rowb + hpb + u * 2] = hh[u];
    }
}

// out[b] = relu(dot(h_T[b,:], Wl) + bl) ; h stored k-permuted -> index Wl via inverse perm
__global__ void head_kernel(const float* __restrict__ Wl,
                            const float* __restrict__ bl,
                            float* __restrict__ out, int sel) {
    int b = blockIdx.x;
    const float* __restrict__ h = g_h[sel] + (size_t)b * HH;
    float s = 0.0f;
    for (int i = threadIdx.x; i < HH; i += blockDim.x)
        s += h[i] * Wl[kinv(i)];
#pragma unroll
    for (int o = 16; o; o >>= 1) s += __shfl_down_sync(0xffffffffu, s, o);
    __shared__ float red[8];
    if ((threadIdx.x & 31) == 0) red[threadIdx.x >> 5] = s;
    __syncthreads();
    if (threadIdx.x < 32) {
        s = (threadIdx.x < (blockDim.x >> 5)) ? red[threadIdx.x] : 0.0f;
#pragma unroll
        for (int o = 4; o; o >>= 1) s += __shfl_down_sync(0xffffffffu, s, o);
        if (threadIdx.x == 0) out[b] = fmaxf(s + bl[0], 0.0f);
    }
}

extern "C" void kernel_launch(void* const* d_in, const int* in_sizes, int n_in,
                              void* d_out, int out_size) {
    const float* xd   = (const float*)d_in[0];
    const float* Wih  = (const float*)d_in[1];
    const float* Whh  = (const float*)d_in[2];
    const float* bias = (const float*)d_in[3];
    const float* Wl   = (const float*)d_in[4];
    const float* bl   = (const float*)d_in[5];
    float* out = (float*)d_out;

    cudaFuncSetAttribute(step_kernel,
                         cudaFuncAttributeMaxDynamicSharedMemorySize, SMEM_BYTES);

    prep_kernel<<<(G4 * KK + 255) / 256, 256>>>(Wih, Whh, bias);
    zero_kernel<<<(Bsz * HH + 255) / 256, 256>>>();

    for (int t = 0; t < TT; t++) {
        step_kernel<<<dim3(G4 / BN, Bsz / BM), 256, SMEM_BYTES>>>(xd, t, t & 1);
    }
    // t=729 (odd) writes g_h[0]
    head_kernel<<<Bsz, 256>>>(Wl, bl, out, 0);
}

// round 7
// speedup vs baseline: 5.7364x; 1.8385x over previous
#include <cuda_runtime.h>
#include <cuda_fp16.h>
#include <math.h>
#include <stdint.h>

#define Bsz 1024
#define TT  730
#define INN 64
#define HH  512
#define KK  576
#define G4  2048

#define BM 128
#define BN 128
#define BK 64                     // halfs per chunk (128 bytes per row)
#define NCHUNK 9
#define NSTAGE 3

#define A_TILE_B 16384            // 128 rows x 128 B
#define B_TILE_B 16384
#define STAGE_B  (A_TILE_B + B_TILE_B)
#define SMEM_BYTES (NSTAGE * STAGE_B)   // 98304
#define ZS_STRIDE 132

// ---- device-global scratch (allocation-free) ----
__device__ __half g_Wc[(size_t)G4 * KK];          // [colp][kpos] fp16, permuted both axes
__device__ float  g_bperm[G4];
__device__ __half g_x16[(size_t)TT * Bsz * INN];  // [t][b][kpos] fp16, k sigma-permuted
__device__ __half g_h[2][Bsz * HH];               // hidden state, sigma-permuted positions
__device__ float  g_c[Bsz * HH];                  // cell state (indexed by stored position)

// sigma: within each 16-block, stored position p holds actual index invs16(p)
// (so that thread tig's fragment halfs {2t,2t+1,2t+8,2t+9} sit at positions 4t..4t+3)
__device__ __host__ __forceinline__ int invs16(int p) {
    return (p & 1) | (((p >> 2) & 3) << 1) | (((p >> 1) & 1) << 3);
}
__device__ __forceinline__ int invs(int p) {       // full (any multiple of 16)
    return (p & ~15) | invs16(p & 15);
}

__device__ __forceinline__ unsigned h2_as_u32(__half2 h) {
    union { __half2 h; unsigned u; } cvt;
    cvt.h = h;
    return cvt.u;
}

__device__ __forceinline__ void cpa16(void* dst, const void* src) {
    unsigned d = (unsigned)__cvta_generic_to_shared(dst);
    asm volatile("cp.async.cg.shared.global [%0], [%1], 16;" :: "r"(d), "l"(src));
}
#define CP_COMMIT() asm volatile("cp.async.commit_group;")
#define CP_WAIT(n)  asm volatile("cp.async.wait_group %0;" :: "n"(n) : "memory")

#define MMA_F16(d, a, b)                                                      \
    asm volatile(                                                             \
        "mma.sync.aligned.m16n8k16.row.col.f32.f16.f16.f32 "                  \
        "{%0,%1,%2,%3}, {%4,%5,%6,%7}, {%8,%9}, {%0,%1,%2,%3};"               \
        : "+f"((d)[0]), "+f"((d)[1]), "+f"((d)[2]), "+f"((d)[3])              \
        : "r"((a)[0]), "r"((a)[1]), "r"((a)[2]), "r"((a)[3]),                 \
          "r"((b)[0]), "r"((b)[1]))

// ---------------- prep ----------------
// Weights: g_Wc[colp*576 + kpos]; colp = hpos*4 + g, actual h = invs(hpos);
// k column kpos multiplies stored A position kpos => actual k = invs(kpos).
__global__ void prep_w_kernel(const float* __restrict__ Wih,
                              const float* __restrict__ Whh,
                              const float* __restrict__ bias) {
    int idx = blockIdx.x * blockDim.x + threadIdx.x;
    if (idx >= G4 * KK) return;
    int colp = idx / KK;
    int kpos = idx % KK;
    int hpos = colp >> 2, g = colp & 3;
    int h_act = invs(hpos);
    int k_act = invs(kpos);
    int w = g * HH + h_act;
    float v = (k_act < INN) ? Wih[(size_t)w * INN + k_act]
                            : Whh[(size_t)w * HH + (k_act - INN)];
    g_Wc[idx] = __float2half(v);
    if (idx < G4) g_bperm[idx] = bias[(idx & 3) * HH + invs(idx >> 2)];
}

// x16[t][b][kpos] = fp16(xd[b][t][invs(kpos)])
__global__ void prep_x_kernel(const float* __restrict__ xd) {
    size_t idx = (size_t)blockIdx.x * blockDim.x + threadIdx.x;
    if (idx >= (size_t)TT * Bsz * INN) return;
    int kpos = (int)(idx & 63);
    int b    = (int)((idx >> 6) & 1023);
    int t    = (int)(idx >> 16);
    g_x16[idx] = __float2half(xd[(size_t)b * TT * INN + (size_t)t * INN + invs(kpos)]);
}

__global__ void zero_kernel() {
    int idx = blockIdx.x * blockDim.x + threadIdx.x;
    if (idx < Bsz * HH) {
        g_h[0][idx] = __float2half(0.0f);
        g_c[idx] = 0.0f;
    }
}

__device__ __forceinline__ float sigf(float x) {
    return __fdividef(1.0f, 1.0f + __expf(-x));
}
__device__ __forceinline__ float tanhfast(float x) {
    return fmaf(2.0f, sigf(2.0f * x), -1.0f);
}

// ---------------- one LSTM step ----------------
__global__ __launch_bounds__(256, 1)
void step_kernel(int t, int sel) {
    extern __shared__ char smem[];
    float* Zs = (float*)smem;   // epilogue reuse

    const __half* __restrict__ hprev = g_h[sel];
    __half* __restrict__ hnew = g_h[sel ^ 1];

    const int tid  = threadIdx.x;
    const int lane = tid & 31;
    const int wid  = tid >> 5;
    const int grp  = lane >> 2;
    const int tig  = lane & 3;
    const int wm   = wid & 1;     // 2 warps over M
    const int wn   = wid >> 1;    // 4 warps over N

    const int nt = blockIdx.x, mt = blockIdx.y;
    const int n0 = nt * BN, b0 = mt * BM;

    float acc[4][4][4];
#pragma unroll
    for (int mf = 0; mf < 4; mf++)
#pragma unroll
        for (int nf = 0; nf < 4; nf++)
#pragma unroll
            for (int r = 0; r < 4; r++) acc[mf][nf][r] = 0.0f;

    // fragment smem byte offsets within a 128B row, XOR-swizzled, per k16 slice
    const int xorb = ((grp & 1) << 6) | ((grp & 2) << 4);
    int koff[4];
#pragma unroll
    for (int ks = 0; ks < 4; ks++) koff[ks] = (ks * 32 + tig * 8) ^ xorb;

    // loader: chunk kc -> stage kc % NSTAGE. 16B chunks, swizzled dst.
    auto load_chunk = [&](int kc) {
        char* Ab = smem + (kc % NSTAGE) * STAGE_B;
        char* Bb = Ab + A_TILE_B;
#pragma unroll
        for (int i = 0; i < 4; i++) {
            int u = i * 256 + tid;          // 0..1023
            int r = u >> 3, cq = u & 7;
            int fc = ((r & 1) << 2) | (r & 2);
            char* dst = Ab + r * 128 + ((cq ^ fc) << 4);
            const __half* src = (kc == 0)
                ? g_x16 + ((size_t)t * Bsz + b0 + r) * INN + cq * 8
                : hprev + ((size_t)(b0 + r) << 9) + (kc - 1) * 64 + cq * 8;
            cpa16(dst, src);
        }
#pragma unroll
        for (int i = 0; i < 4; i++) {
            int u = i * 256 + tid;
            int r = u >> 3, cq = u & 7;
            int fc = ((r & 1) << 2) | (r & 2);
            char* dst = Bb + r * 128 + ((cq ^ fc) << 4);
            cpa16(dst, g_Wc + (size_t)(n0 + r) * KK + kc * 64 + cq * 8);
        }
        CP_COMMIT();
    };

    load_chunk(0);
    load_chunk(1);

#pragma unroll 1
    for (int kc = 0; kc < NCHUNK; kc++) {
        if (kc == NCHUNK - 1) CP_WAIT(0); else CP_WAIT(1);
        __syncthreads();

        if (kc + 2 < NCHUNK) load_chunk(kc + 2);

        const char* Ab = smem + (kc % NSTAGE) * STAGE_B;
        const char* Bb = Ab + A_TILE_B;
#pragma unroll
        for (int ks = 0; ks < 4; ks++) {
            unsigned a[4][4], b[4][2];
#pragma unroll
            for (int mf = 0; mf < 4; mf++) {
                int r0 = wm * 64 + mf * 16 + grp;
                uint2 lo = *(const uint2*)(Ab + r0 * 128 + koff[ks]);        // a0,a2
                uint2 hi = *(const uint2*)(Ab + (r0 + 8) * 128 + koff[ks]);  // a1,a3
                a[mf][0] = lo.x; a[mf][1] = hi.x; a[mf][2] = lo.y; a[mf][3] = hi.y;
            }
#pragma unroll
            for (int nf = 0; nf < 4; nf++) {
                int c0 = wn * 32 + nf * 8 + grp;
                uint2 bv = *(const uint2*)(Bb + c0 * 128 + koff[ks]);
                b[nf][0] = bv.x; b[nf][1] = bv.y;
            }
#pragma unroll
            for (int mf = 0; mf < 4; mf++)
#pragma unroll
                for (int nf = 0; nf < 4; nf++)
                    MMA_F16(acc[mf][nf], a[mf], b[nf]);
        }
    }

    // ---- epilogue: z -> smem (gate quads contiguous), then gate math ----
    __syncthreads();
#pragma unroll
    for (int mf = 0; mf < 4; mf++) {
        int row = wm * 64 + mf * 16 + grp;
#pragma unroll
        for (int nf = 0; nf < 4; nf++) {
            int col = wn * 32 + nf * 8 + tig * 2;
            *(float2*)&Zs[row * ZS_STRIDE + col] =
                make_float2(acc[mf][nf][0], acc[mf][nf][1]);
            *(float2*)&Zs[(row + 8) * ZS_STRIDE + col] =
                make_float2(acc[mf][nf][2], acc[mf][nf][3]);
        }
    }
    __syncthreads();

    const int hq = tid & 7;            // h-quad within the CTA's 32 h-positions
    float4 bq[4];
#pragma unroll
    for (int u = 0; u < 4; u++)
        bq[u] = *(const float4*)&g_bperm[n0 + (hq * 4 + u) * 4];

#pragma unroll
    for (int p = 0; p < 4; p++) {
        int bl = p * 32 + (tid >> 3);
        size_t rowb = (size_t)(b0 + bl) * HH;
        size_t cidx = rowb + nt * 32 + hq * 4;
        float4 cv = *(float4*)&g_c[cidx];
        float cin[4] = {cv.x, cv.y, cv.z, cv.w};
        float cc[4], hh[4];
#pragma unroll
        for (int u = 0; u < 4; u++) {
            float4 z = *(float4*)&Zs[bl * ZS_STRIDE + (hq * 4 + u) * 4];
            float zi = z.x + bq[u].x;
            float zf = z.y + bq[u].y;
            float zg = z.z + bq[u].z;
            float zo = z.w + bq[u].w;
            float ig = sigf(zi), fg = sigf(zf);
            float gg = tanhfast(zg), og = sigf(zo);
            float cn = fmaf(fg, cin[u], ig * gg);
            cc[u] = cn;
            hh[u] = og * tanhfast(cn);
        }
        *(float4*)&g_c[cidx] = make_float4(cc[0], cc[1], cc[2], cc[3]);
        uint2 hv;
        hv.x = h2_as_u32(__floats2half2_rn(hh[0], hh[1]));
        hv.y = h2_as_u32(__floats2half2_rn(hh[2], hh[3]));
        *(uint2*)&hnew[cidx] = hv;
    }
}

// out[b] = relu(dot(h_T[b,:], Wl) + bl) ; h stored permuted -> Wl via invs
__global__ void head_kernel(const float* __restrict__ Wl,
                            const float* __restrict__ bl,
                            float* __restrict__ out, int sel) {
    int b = blockIdx.x;
    const __half* __restrict__ h = g_h[sel] + (size_t)b * HH;
    float s = 0.0f;
    for (int i = threadIdx.x; i < HH; i += blockDim.x)
        s += __half2float(h[i]) * Wl[invs(i)];
#pragma unroll
    for (int o = 16; o; o >>= 1) s += __shfl_down_sync(0xffffffffu, s, o);
    __shared__ float red[8];
    if ((threadIdx.x & 31) == 0) red[threadIdx.x >> 5] = s;
    __syncthreads();
    if (threadIdx.x < 32) {
        s = (threadIdx.x < (blockDim.x >> 5)) ? red[threadIdx.x] : 0.0f;
#pragma unroll
        for (int o = 4; o; o >>= 1) s += __shfl_down_sync(0xffffffffu, s, o);
        if (threadIdx.x == 0) out[b] = fmaxf(s + bl[0], 0.0f);
    }
}

extern "C" void kernel_launch(void* const* d_in, const int* in_sizes, int n_in,
                              void* d_out, int out_size) {
    const float* xd   = (const float*)d_in[0];
    const float* Wih  = (const float*)d_in[1];
    const float* Whh  = (const float*)d_in[2];
    const float* bias = (const float*)d_in[3];
    const float* Wl   = (const float*)d_in[4];
    const float* bl   = (const float*)d_in[5];
    float* out = (float*)d_out;

    cudaFuncSetAttribute(step_kernel,
                         cudaFuncAttributeMaxDynamicSharedMemorySize, SMEM_BYTES);

    prep_w_kernel<<<(G4 * KK + 255) / 256, 256>>>(Wih, Whh, bias);
    {
        size_t nx = (size_t)TT * Bsz * INN;
        prep_x_kernel<<<(unsigned)((nx + 255) / 256), 256>>>(xd);
    }
    zero_kernel<<<(Bsz * HH + 255) / 256, 256>>>();

    for (int t = 0; t < TT; t++) {
        step_kernel<<<dim3(G4 / BN, Bsz / BM), 256, SMEM_BYTES>>>(t, t & 1);
    }
    // t=729 (odd) writes g_h[0]
    head_kernel<<<Bsz, 256>>>(Wl, bl, out, 0);
}

// round 8
// speedup vs baseline: 6.1674x; 1.0751x over previous
#include <cuda_runtime.h>
#include <cuda_fp16.h>
#include <math.h>
#include <stdint.h>

#define Bsz 1024
#define TT  730
#define INN 64
#define HH  512
#define KK  576
#define G4  2048

#define BM 128
#define BN 128
#define NCHUNK 9
#define NSTAGE 4

#define A_TILE_B 16384            // 128 rows x 128 B
#define B_TILE_B 16384
#define STAGE_B  (A_TILE_B + B_TILE_B)
#define SMEM_BYTES (NSTAGE * STAGE_B)   // 131072

// ---- device-global scratch (allocation-free) ----
__device__ __half g_Wc[(size_t)G4 * KK];          // [colpos][kpos] fp16 (both axes permuted)
__device__ float  g_bias4[HH * 4];                // [h_pos][gate] biases
__device__ __half g_x16[(size_t)TT * Bsz * INN];  // [t][b][kpos] fp16, k sigma-permuted
__device__ __half g_h[2][Bsz * HH];               // hidden state at sigma positions
__device__ float  g_c[Bsz * HH];                  // cell state (indexed by h position)

// sigma: stored position p holds actual index invs16(p) within each 16-block
// (thread tig's fragment halfs {2t,2t+1,2t+8,2t+9} sit at positions 4t..4t+3)
__device__ __host__ __forceinline__ int invs16(int p) {
    return (p & 1) | (((p >> 2) & 3) << 1) | (((p >> 1) & 1) << 3);
}
__device__ __forceinline__ int invs(int p) {
    return (p & ~15) | invs16(p & 15);
}

__device__ __forceinline__ unsigned h2_as_u32(__half2 h) {
    union { __half2 h; unsigned u; } cvt;
    cvt.h = h;
    return cvt.u;
}

__device__ __forceinline__ void cpa16(void* dst, const void* src) {
    unsigned d = (unsigned)__cvta_generic_to_shared(dst);
    asm volatile("cp.async.cg.shared.global [%0], [%1], 16;" :: "r"(d), "l"(src));
}
#define CP_COMMIT() asm volatile("cp.async.commit_group;")
#define CP_WAIT(n)  asm volatile("cp.async.wait_group %0;" :: "n"(n) : "memory")

#define MMA_F16(d, a, b)                                                      \
    asm volatile(                                                             \
        "mma.sync.aligned.m16n8k16.row.col.f32.f16.f16.f32 "                  \
        "{%0,%1,%2,%3}, {%4,%5,%6,%7}, {%8,%9}, {%0,%1,%2,%3};"               \
        : "+f"((d)[0]), "+f"((d)[1]), "+f"((d)[2]), "+f"((d)[3])              \
        : "r"((a)[0]), "r"((a)[1]), "r"((a)[2]), "r"((a)[3]),                 \
          "r"((b)[0]), "r"((b)[1]))

// ---------------- prep ----------------
// Column position p (0..2047): nt=p>>7, loc=p&127, wn=(loc>>5), g=(loc>>3)&3, hl=loc&7.
// h position q = nt*32 + wn*8 + hl ; actual h = invs(q) ; actual k of row kpos = invs(kpos).
__global__ void prep_w_kernel(const float* __restrict__ Wih,
                              const float* __restrict__ Whh,
                              const float* __restrict__ bias) {
    int idx = blockIdx.x * blockDim.x + threadIdx.x;
    if (idx >= G4 * KK) return;
    int p    = idx / KK;
    int kpos = idx % KK;
    int nt = p >> 7, loc = p & 127;
    int wn = loc >> 5, g = (loc >> 3) & 3, hl = loc & 7;
    int q = nt * 32 + wn * 8 + hl;
    int h_act = invs(q);
    int k_act = invs(kpos);
    int w = g * HH + h_act;
    float v = (k_act < INN) ? Wih[(size_t)w * INN + k_act]
                            : Whh[(size_t)w * HH + (k_act - INN)];
    g_Wc[idx] = __float2half(v);
    if (idx < HH * 4) {
        int qq = idx >> 2, gg = idx & 3;
        g_bias4[idx] = bias[gg * HH + invs(qq)];
    }
}

// x16[t][b][kpos] = fp16(xd[b][t][invs(kpos)])
__global__ void prep_x_kernel(const float* __restrict__ xd) {
    size_t idx = (size_t)blockIdx.x * blockDim.x + threadIdx.x;
    if (idx >= (size_t)TT * Bsz * INN) return;
    int kpos = (int)(idx & 63);
    int b    = (int)((idx >> 6) & 1023);
    int t    = (int)(idx >> 16);
    g_x16[idx] = __float2half(xd[(size_t)b * TT * INN + (size_t)t * INN + invs(kpos)]);
}

__global__ void zero_kernel() {
    int idx = blockIdx.x * blockDim.x + threadIdx.x;
    if (idx < Bsz * HH) {
        g_h[0][idx] = __float2half(0.0f);
        g_c[idx] = 0.0f;
    }
}

__device__ __forceinline__ float sigf(float x) {
    return __fdividef(1.0f, 1.0f + __expf(-x));
}
__device__ __forceinline__ float tanhfast(float x) {
    return fmaf(2.0f, sigf(2.0f * x), -1.0f);
}

// ---------------- one LSTM step ----------------
__global__ __launch_bounds__(512, 1)
void step_kernel(int t, int sel) {
    extern __shared__ char smem[];

    const __half* __restrict__ hprev = g_h[sel];
    __half* __restrict__ hnew = g_h[sel ^ 1];

    const int tid  = threadIdx.x;
    const int lane = tid & 31;
    const int wid  = tid >> 5;
    const int grp  = lane >> 2;
    const int tig  = lane & 3;
    const int wm   = wid & 3;     // 4 warps over M (32 rows each)
    const int wn   = wid >> 2;    // 4 warps over N (32 cols each)

    const int nt = blockIdx.x, mt = blockIdx.y;
    const int n0 = nt * BN, b0 = mt * BM;

    float acc[2][4][4];
#pragma unroll
    for (int mf = 0; mf < 2; mf++)
#pragma unroll
        for (int nf = 0; nf < 4; nf++)
#pragma unroll
            for (int r = 0; r < 4; r++) acc[mf][nf][r] = 0.0f;

    // fragment smem byte offsets within a 128B row, XOR-swizzled, per k16 slice
    const int xorb = ((grp & 1) << 6) | ((grp & 2) << 4);
    int koff[4];
#pragma unroll
    for (int ks = 0; ks < 4; ks++) koff[ks] = (ks * 32 + tig * 8) ^ xorb;

    // loader: chunk kc -> stage kc % NSTAGE. 16B chunks, swizzled dst.
    auto load_chunk = [&](int kc) {
        char* Ab = smem + (kc & 3) * STAGE_B;
        char* Bb = Ab + A_TILE_B;
#pragma unroll
        for (int i = 0; i < 2; i++) {
            int u = i * 512 + tid;          // 0..1023
            int r = u >> 3, cq = u & 7;
            int fc = ((r & 1) << 2) | (r & 2);
            char* dst = Ab + r * 128 + ((cq ^ fc) << 4);
            const __half* src = (kc == 0)
                ? g_x16 + ((size_t)t * Bsz + b0 + r) * INN + cq * 8
                : hprev + ((size_t)(b0 + r) << 9) + (kc - 1) * 64 + cq * 8;
            cpa16(dst, src);
        }
#pragma unroll
        for (int i = 0; i < 2; i++) {
            int u = i * 512 + tid;
            int r = u >> 3, cq = u & 7;
            int fc = ((r & 1) << 2) | (r & 2);
            char* dst = Bb + r * 128 + ((cq ^ fc) << 4);
            cpa16(dst, g_Wc + (size_t)(n0 + r) * KK + kc * 64 + cq * 8);
        }
        CP_COMMIT();
    };

    load_chunk(0);
    load_chunk(1);
    load_chunk(2);

#pragma unroll 1
    for (int kc = 0; kc < NCHUNK; kc++) {
        if (kc >= NCHUNK - 1)      CP_WAIT(0);
        else if (kc == NCHUNK - 2) CP_WAIT(1);
        else                       CP_WAIT(2);
        __syncthreads();

        if (kc + 3 < NCHUNK) load_chunk(kc + 3);

        const char* Ab = smem + (kc & 3) * STAGE_B;
        const char* Bb = Ab + A_TILE_B;
#pragma unroll
        for (int ks = 0; ks < 4; ks++) {
            unsigned a[2][4], b[4][2];
#pragma unroll
            for (int mf = 0; mf < 2; mf++) {
                int r0 = wm * 32 + mf * 16 + grp;
                uint2 lo = *(const uint2*)(Ab + r0 * 128 + koff[ks]);        // a0,a2
                uint2 hi = *(const uint2*)(Ab + (r0 + 8) * 128 + koff[ks]);  // a1,a3
                a[mf][0] = lo.x; a[mf][1] = hi.x; a[mf][2] = lo.y; a[mf][3] = hi.y;
            }
#pragma unroll
            for (int nf = 0; nf < 4; nf++) {
                int c0 = wn * 32 + nf * 8 + grp;
                uint2 bv = *(const uint2*)(Bb + c0 * 128 + koff[ks]);
                b[nf][0] = bv.x; b[nf][1] = bv.y;
            }
#pragma unroll
            for (int mf = 0; mf < 2; mf++)
#pragma unroll
                for (int nf = 0; nf < 4; nf++)
                    MMA_F16(acc[mf][nf], a[mf], b[nf]);
        }
    }

    // ---- epilogue: fully in registers (gates g = nf, h units 2*tig, 2*tig+1) ----
    const int qh = nt * 32 + wn * 8 + tig * 2;   // h position (even)
    float4 bg0 = *(const float4*)&g_bias4[qh * 4];        // gates for h pos qh
    float4 bg1 = *(const float4*)&g_bias4[(qh + 1) * 4];  // gates for h pos qh+1

#pragma unroll
    for (int mf = 0; mf < 2; mf++) {
#pragma unroll
        for (int rr = 0; rr < 2; rr++) {
            int b = b0 + wm * 32 + mf * 16 + grp + rr * 8;
            size_t cidx = (size_t)b * HH + qh;
            float2 cv = *(float2*)&g_c[cidx];
            float hh0, hh1;
            {
                int j = rr * 2 + 0;
                float zi = acc[mf][0][j] + bg0.x;
                float zf = acc[mf][1][j] + bg0.y;
                float zg = acc[mf][2][j] + bg0.z;
                float zo = acc[mf][3][j] + bg0.w;
                float cn = fmaf(sigf(zf), cv.x, sigf(zi) * tanhfast(zg));
                cv.x = cn;
                hh0 = sigf(zo) * tanhfast(cn);
            }
            {
                int j = rr * 2 + 1;
                float zi = acc[mf][0][j] + bg1.x;
                float zf = acc[mf][1][j] + bg1.y;
                float zg = acc[mf][2][j] + bg1.z;
                float zo = acc[mf][3][j] + bg1.w;
                float cn = fmaf(sigf(zf), cv.y, sigf(zi) * tanhfast(zg));
                cv.y = cn;
                hh1 = sigf(zo) * tanhfast(cn);
            }
            *(float2*)&g_c[cidx] = cv;
            *(unsigned*)&hnew[cidx] = h2_as_u32(__floats2half2_rn(hh0, hh1));
        }
    }
}

// out[b] = relu(dot(h_T[b,:], Wl) + bl) ; h stored permuted -> Wl via invs
__global__ void head_kernel(const float* __restrict__ Wl,
                            const float* __restrict__ bl,
                            float* __restrict__ out, int sel) {
    int b = blockIdx.x;
    const __half* __restrict__ h = g_h[sel] + (size_t)b * HH;
    float s = 0.0f;
    for (int i = threadIdx.x; i < HH; i += blockDim.x)
        s += __half2float(h[i]) * Wl[invs(i)];
#pragma unroll
    for (int o = 16; o; o >>= 1) s += __shfl_down_sync(0xffffffffu, s, o);
    __shared__ float red[8];
    if ((threadIdx.x & 31) == 0) red[threadIdx.x >> 5] = s;
    __syncthreads();
    if (threadIdx.x < 32) {
        s = (threadIdx.x < (blockDim.x >> 5)) ? red[threadIdx.x] : 0.0f;
#pragma unroll
        for (int o = 4; o; o >>= 1) s += __shfl_down_sync(0xffffffffu, s, o);
        if (threadIdx.x == 0) out[b] = fmaxf(s + bl[0], 0.0f);
    }
}

extern "C" void kernel_launch(void* const* d_in, const int* in_sizes, int n_in,
                              void* d_out, int out_size) {
    const float* xd   = (const float*)d_in[0];
    const float* Wih  = (const float*)d_in[1];
    const float* Whh  = (const float*)d_in[2];
    const float* bias = (const float*)d_in[3];
    const float* Wl   = (const float*)d_in[4];
    const float* bl   = (const float*)d_in[5];
    float* out = (float*)d_out;

    cudaFuncSetAttribute(step_kernel,
                         cudaFuncAttributeMaxDynamicSharedMemorySize, SMEM_BYTES);

    prep_w_kernel<<<(G4 * KK + 255) / 256, 256>>>(Wih, Whh, bias);
    {
        size_t nx = (size_t)TT * Bsz * INN;
        prep_x_kernel<<<(unsigned)((nx + 255) / 256), 256>>>(xd);
    }
    zero_kernel<<<(Bsz * HH + 255) / 256, 256>>>();

    for (int t = 0; t < TT; t++) {
        step_kernel<<<dim3(G4 / BN, Bsz / BM), 512, SMEM_BYTES>>>(t, t & 1);
    }
    // t=729 (odd) writes g_h[0]
    head_kernel<<<Bsz, 256>>>(Wl, bl, out, 0);
}

// round 9
// speedup vs baseline: 6.8046x; 1.1033x over previous
#include <cuda_runtime.h>
#include <cuda_fp16.h>
#include <math.h>
#include <stdint.h>

#define Bsz 1024
#define TT  730
#define INN 64
#define HH  512
#define KK  576
#define G4  2048

#define BM 128
#define BN 128
#define NCHUNK 9
#define NGRID 128                  // total CTAs (must all be co-resident)

#define CHUNK_B 16384              // 128 rows x 128 B
#define B_RES_B (NCHUNK * CHUNK_B) // 147456: resident weights
#define A_STG_B (4 * CHUNK_B)      // 65536: 4-stage A pipeline
#define SMEM_BYTES (B_RES_B + A_STG_B)   // 212992

// ---- device-global scratch (allocation-free) ----
__device__ __half g_Wc[(size_t)G4 * KK];          // [colpos][kpos] fp16 (both axes permuted)
__device__ float  g_bias4[HH * 4];                // [h_pos][gate]
__device__ __half g_x16[(size_t)TT * Bsz * INN];  // [t][b][kpos] fp16
__device__ __half g_h[2][Bsz * HH];               // hidden state at sigma positions
__device__ float  g_c[Bsz * HH];                  // cell state
__device__ unsigned g_bar;                        // grid barrier counter

__device__ __host__ __forceinline__ int invs16(int p) {
    return (p & 1) | (((p >> 2) & 3) << 1) | (((p >> 1) & 1) << 3);
}
__device__ __forceinline__ int invs(int p) {
    return (p & ~15) | invs16(p & 15);
}

__device__ __forceinline__ unsigned h2_as_u32(__half2 h) {
    union { __half2 h; unsigned u; } cvt;
    cvt.h = h;
    return cvt.u;
}

__device__ __forceinline__ void cpa16(void* dst, const void* src) {
    unsigned d = (unsigned)__cvta_generic_to_shared(dst);
    asm volatile("cp.async.cg.shared.global [%0], [%1], 16;" :: "r"(d), "l"(src));
}
#define CP_COMMIT() asm volatile("cp.async.commit_group;")
#define CP_WAIT(n)  asm volatile("cp.async.wait_group %0;" :: "n"(n) : "memory")

#define MMA_F16(d, a, b)                                                      \
    asm volatile(                                                             \
        "mma.sync.aligned.m16n8k16.row.col.f32.f16.f16.f32 "                  \
        "{%0,%1,%2,%3}, {%4,%5,%6,%7}, {%8,%9}, {%0,%1,%2,%3};"               \
        : "+f"((d)[0]), "+f"((d)[1]), "+f"((d)[2]), "+f"((d)[3])              \
        : "r"((a)[0]), "r"((a)[1]), "r"((a)[2]), "r"((a)[3]),                 \
          "r"((b)[0]), "r"((b)[1]))

// ---------------- prep (identical mappings to R8) ----------------
__global__ void prep_w_kernel(const float* __restrict__ Wih,
                              const float* __restrict__ Whh,
                              const float* __restrict__ bias) {
    int idx = blockIdx.x * blockDim.x + threadIdx.x;
    if (idx >= G4 * KK) return;
    int p    = idx / KK;
    int kpos = idx % KK;
    int nt = p >> 7, loc = p & 127;
    int wn = loc >> 5, g = (loc >> 3) & 3, hl = loc & 7;
    int q = nt * 32 + wn * 8 + hl;
    int h_act = invs(q);
    int k_act = invs(kpos);
    int w = g * HH + h_act;
    float v = (k_act < INN) ? Wih[(size_t)w * INN + k_act]
                            : Whh[(size_t)w * HH + (k_act - INN)];
    g_Wc[idx] = __float2half(v);
    if (idx < HH * 4) {
        int qq = idx >> 2, gg = idx & 3;
        g_bias4[idx] = bias[gg * HH + invs(qq)];
    }
}

__global__ void prep_x_kernel(const float* __restrict__ xd) {
    size_t idx = (size_t)blockIdx.x * blockDim.x + threadIdx.x;
    if (idx >= (size_t)TT * Bsz * INN) return;
    int kpos = (int)(idx & 63);
    int b    = (int)((idx >> 6) & 1023);
    int t    = (int)(idx >> 16);
    g_x16[idx] = __float2half(xd[(size_t)b * TT * INN + (size_t)t * INN + invs(kpos)]);
}

__global__ void zero_kernel() {
    int idx = blockIdx.x * blockDim.x + threadIdx.x;
    if (idx < Bsz * HH) {
        g_h[0][idx] = __float2half(0.0f);
        g_c[idx] = 0.0f;
    }
    if (idx == 0) g_bar = 0;
}

__device__ __forceinline__ float sigf(float x) {
    return __fdividef(1.0f, 1.0f + __expf(-x));
}
__device__ __forceinline__ float tanhfast(float x) {
    return fmaf(2.0f, sigf(2.0f * x), -1.0f);
}

// ---------------- persistent LSTM: all 730 steps in one launch ----------------
__global__ __launch_bounds__(512, 1)
void lstm_persist_kernel() {
    extern __shared__ char smem[];
    char* Bres = smem;               // 9 chunks x 16KB resident weights
    char* Astg = smem + B_RES_B;     // 4 stages x 16KB A pipeline

    const int tid  = threadIdx.x;
    const int lane = tid & 31;
    const int wid  = tid >> 5;
    const int grp  = lane >> 2;
    const int tig  = lane & 3;
    const int wm   = wid & 3;
    const int wn   = wid >> 2;

    const int nt = blockIdx.x, mt = blockIdx.y;
    const int n0 = nt * BN, b0 = mt * BM;

    // ---- resident B load (once) ----
#pragma unroll
    for (int i = 0; i < 18; i++) {
        int u = i * 512 + tid;            // 0..9215 16B-units
        int kc  = u >> 10;
        int rem = u & 1023;
        int c = rem >> 3, cq = rem & 7;
        int fc = ((c & 1) << 2) | (c & 2);
        cpa16(Bres + kc * CHUNK_B + c * 128 + ((cq ^ fc) << 4),
              g_Wc + (size_t)(n0 + c) * KK + kc * 64 + cq * 8);
    }
    CP_COMMIT();

    const int xorb = ((grp & 1) << 6) | ((grp & 2) << 4);
    int koff[4];
#pragma unroll
    for (int ks = 0; ks < 4; ks++) koff[ks] = (ks * 32 + tig * 8) ^ xorb;

    auto load_x = [&](int t, int stage) {
        char* Ab = Astg + stage * CHUNK_B;
#pragma unroll
        for (int i = 0; i < 2; i++) {
            int u = i * 512 + tid;
            int r = u >> 3, cq = u & 7;
            int fc = ((r & 1) << 2) | (r & 2);
            cpa16(Ab + r * 128 + ((cq ^ fc) << 4),
                  g_x16 + ((size_t)t * Bsz + b0 + r) * INN + cq * 8);
        }
        CP_COMMIT();
    };
    auto load_h = [&](const __half* hp, int kc, int stage) {   // kc in 1..8
        char* Ab = Astg + stage * CHUNK_B;
#pragma unroll
        for (int i = 0; i < 2; i++) {
            int u = i * 512 + tid;
            int r = u >> 3, cq = u & 7;
            int fc = ((r & 1) << 2) | (r & 2);
            cpa16(Ab + r * 128 + ((cq ^ fc) << 4),
                  hp + ((size_t)(b0 + r) << 9) + (kc - 1) * 64 + cq * 8);
        }
        CP_COMMIT();
    };

    CP_WAIT(0);           // B resident
    __syncthreads();

    // prologue for t=0: chunk kc of step t lives in stage (t+kc)&3
    load_x(0, 0);
    load_h(g_h[0], 1, 1);
    load_h(g_h[0], 2, 2);

    const int qh = nt * 32 + wn * 8 + tig * 2;
    const float4 bg0 = *(const float4*)&g_bias4[qh * 4];
    const float4 bg1 = *(const float4*)&g_bias4[(qh + 1) * 4];

#pragma unroll 1
    for (int t = 0; t < TT; t++) {
        const __half* __restrict__ hprev = g_h[t & 1];
        __half* __restrict__ hnew = g_h[(t & 1) ^ 1];

        float acc[2][4][4];
#pragma unroll
        for (int mf = 0; mf < 2; mf++)
#pragma unroll
            for (int nf = 0; nf < 4; nf++)
#pragma unroll
                for (int r = 0; r < 4; r++) acc[mf][nf][r] = 0.0f;

#pragma unroll 1
        for (int kc = 0; kc < NCHUNK; kc++) {
            if (kc == NCHUNK - 1) CP_WAIT(1); else CP_WAIT(2);
            __syncthreads();

            if (kc + 3 < NCHUNK) {
                load_h(hprev, kc + 3, (t + kc + 3) & 3);
            } else if (kc == 6) {
                load_x(t + 1 < TT ? t + 1 : 0, (t + 9) & 3);   // cross-step x prefetch
            }

            const char* Ab = Astg + ((t + kc) & 3) * CHUNK_B;
            const char* Bb = Bres + kc * CHUNK_B;
#pragma unroll
            for (int ks = 0; ks < 4; ks++) {
                unsigned a[2][4], b[4][2];
#pragma unroll
                for (int mf = 0; mf < 2; mf++) {
                    int r0 = wm * 32 + mf * 16 + grp;
                    uint2 lo = *(const uint2*)(Ab + r0 * 128 + koff[ks]);
                    uint2 hi = *(const uint2*)(Ab + (r0 + 8) * 128 + koff[ks]);
                    a[mf][0] = lo.x; a[mf][1] = hi.x; a[mf][2] = lo.y; a[mf][3] = hi.y;
                }
#pragma unroll
                for (int nf = 0; nf < 4; nf++) {
                    int c0 = wn * 32 + nf * 8 + grp;
                    uint2 bv = *(const uint2*)(Bb + c0 * 128 + koff[ks]);
                    b[nf][0] = bv.x; b[nf][1] = bv.y;
                }
#pragma unroll
                for (int mf = 0; mf < 2; mf++)
#pragma unroll
                    for (int nf = 0; nf < 4; nf++)
                        MMA_F16(acc[mf][nf], a[mf], b[nf]);
            }
        }

        // ---- register epilogue ----
#pragma unroll
        for (int mf = 0; mf < 2; mf++) {
#pragma unroll
            for (int rr = 0; rr < 2; rr++) {
                int b = b0 + wm * 32 + mf * 16 + grp + rr * 8;
                size_t cidx = (size_t)b * HH + qh;
                float2 cv = *(float2*)&g_c[cidx];
                float hh0, hh1;
                {
                    int j = rr * 2 + 0;
                    float zi = acc[mf][0][j] + bg0.x;
                    float zf = acc[mf][1][j] + bg0.y;
                    float zg = acc[mf][2][j] + bg0.z;
                    float zo = acc[mf][3][j] + bg0.w;
                    float cn = fmaf(sigf(zf), cv.x, sigf(zi) * tanhfast(zg));
                    cv.x = cn;
                    hh0 = sigf(zo) * tanhfast(cn);
                }
                {
                    int j = rr * 2 + 1;
                    float zi = acc[mf][0][j] + bg1.x;
                    float zf = acc[mf][1][j] + bg1.y;
                    float zg = acc[mf][2][j] + bg1.z;
                    float zo = acc[mf][3][j] + bg1.w;
                    float cn = fmaf(sigf(zf), cv.y, sigf(zi) * tanhfast(zg));
                    cv.y = cn;
                    hh1 = sigf(zo) * tanhfast(cn);
                }
                *(float2*)&g_c[cidx] = cv;
                *(unsigned*)&hnew[cidx] = h2_as_u32(__floats2half2_rn(hh0, hh1));
            }
        }

        // ---- grid barrier ----
        __threadfence();
        __syncthreads();
        if (tid == 0) {
            atomicAdd(&g_bar, 1u);
            unsigned target = (unsigned)NGRID * (unsigned)(t + 1);
            while (*(volatile unsigned*)&g_bar < target) { }
        }
        __syncthreads();

        // post-barrier: first h chunks of next step
        if (t + 1 < TT) {
            const __half* hp2 = g_h[(t + 1) & 1];
            load_h(hp2, 1, (t + 2) & 3);
            load_h(hp2, 2, (t + 3) & 3);
        }
    }
}

// out[b] = relu(dot(h_T[b,:], Wl) + bl)
__global__ void head_kernel(const float* __restrict__ Wl,
                            const float* __restrict__ bl,
                            float* __restrict__ out, int sel) {
    int b = blockIdx.x;
    const __half* __restrict__ h = g_h[sel] + (size_t)b * HH;
    float s = 0.0f;
    for (int i = threadIdx.x; i < HH; i += blockDim.x)
        s += __half2float(h[i]) * Wl[invs(i)];
#pragma unroll
    for (int o = 16; o; o >>= 1) s += __shfl_down_sync(0xffffffffu, s, o);
    __shared__ float red[8];
    if ((threadIdx.x & 31) == 0) red[threadIdx.x >> 5] = s;
    __syncthreads();
    if (threadIdx.x < 32) {
        s = (threadIdx.x < (blockDim.x >> 5)) ? red[threadIdx.x] : 0.0f;
#pragma unroll
        for (int o = 4; o; o >>= 1) s += __shfl_down_sync(0xffffffffu, s, o);
        if (threadIdx.x == 0) out[b] = fmaxf(s + bl[0], 0.0f);
    }
}

extern "C" void kernel_launch(void* const* d_in, const int* in_sizes, int n_in,
                              void* d_out, int out_size) {
    const float* xd   = (const float*)d_in[0];
    const float* Wih  = (const float*)d_in[1];
    const float* Whh  = (const float*)d_in[2];
    const float* bias = (const float*)d_in[3];
    const float* Wl   = (const float*)d_in[4];
    const float* bl   = (const float*)d_in[5];
    float* out = (float*)d_out;

    cudaFuncSetAttribute(lstm_persist_kernel,
                         cudaFuncAttributeMaxDynamicSharedMemorySize, SMEM_BYTES);

    prep_w_kernel<<<(G4 * KK + 255) / 256, 256>>>(Wih, Whh, bias);
    {
        size_t nx = (size_t)TT * Bsz * INN;
        prep_x_kernel<<<(unsigned)((nx + 255) / 256), 256>>>(xd);
    }
    zero_kernel<<<(Bsz * HH + 255) / 256, 256>>>();

    lstm_persist_kernel<<<dim3(G4 / BN, Bsz / BM), 512, SMEM_BYTES>>>();

    // final h in g_h[0] (t=729: (729&1)^1 = 0)
    head_kernel<<<Bsz, 256>>>(Wl, bl, out, 0);
}

// round 10
// speedup vs baseline: 7.2343x; 1.0631x over previous
#include <cuda_runtime.h>
#include <cuda_fp16.h>
#include <math.h>
#include <stdint.h>

#define Bsz 1024
#define TT  730
#define INN 64
#define HH  512
#define KK  576
#define G4  2048

#define BM 128
#define BN 128
#define NCHUNK 9
#define GROUP_CTAS 16              // CTAs per mt-group (all nt)

#define CHUNK_B 16384              // 128 rows x 128 B
#define B_RES_B (NCHUNK * CHUNK_B) // 147456: resident weights
#define A_STG_B (4 * CHUNK_B)      // 65536: 4-stage A pipeline
#define SMEM_BYTES (B_RES_B + A_STG_B)   // 212992

// ---- device-global scratch (allocation-free) ----
__device__ __half g_Wc[(size_t)G4 * KK];          // [colpos][kpos] fp16 (both axes permuted)
__device__ float  g_bias4[HH * 4];                // [h_pos][gate]
__device__ __half g_x16[(size_t)TT * Bsz * INN];  // [t][b][kpos] fp16
__device__ __half g_h[2][Bsz * HH];               // hidden state at sigma positions
__device__ unsigned g_barr[8];                    // per-mt group barrier counters

__device__ __host__ __forceinline__ int invs16(int p) {
    return (p & 1) | (((p >> 2) & 3) << 1) | (((p >> 1) & 1) << 3);
}
__device__ __forceinline__ int invs(int p) {
    return (p & ~15) | invs16(p & 15);
}

__device__ __forceinline__ unsigned h2_as_u32(__half2 h) {
    union { __half2 h; unsigned u; } cvt;
    cvt.h = h;
    return cvt.u;
}

__device__ __forceinline__ void cpa16(void* dst, const void* src) {
    unsigned d = (unsigned)__cvta_generic_to_shared(dst);
    asm volatile("cp.async.cg.shared.global [%0], [%1], 16;" :: "r"(d), "l"(src));
}
#define CP_COMMIT() asm volatile("cp.async.commit_group;")
#define CP_WAIT(n)  asm volatile("cp.async.wait_group %0;" :: "n"(n) : "memory")

#define MMA_F16(d, a, b)                                                      \
    asm volatile(                                                             \
        "mma.sync.aligned.m16n8k16.row.col.f32.f16.f16.f32 "                  \
        "{%0,%1,%2,%3}, {%4,%5,%6,%7}, {%8,%9}, {%0,%1,%2,%3};"               \
        : "+f"((d)[0]), "+f"((d)[1]), "+f"((d)[2]), "+f"((d)[3])              \
        : "r"((a)[0]), "r"((a)[1]), "r"((a)[2]), "r"((a)[3]),                 \
          "r"((b)[0]), "r"((b)[1]))

// ---------------- prep (identical mappings to R8/R9) ----------------
__global__ void prep_w_kernel(const float* __restrict__ Wih,
                              const float* __restrict__ Whh,
                              const float* __restrict__ bias) {
    int idx = blockIdx.x * blockDim.x + threadIdx.x;
    if (idx >= G4 * KK) return;
    int p    = idx / KK;
    int kpos = idx % KK;
    int nt = p >> 7, loc = p & 127;
    int wn = loc >> 5, g = (loc >> 3) & 3, hl = loc & 7;
    int q = nt * 32 + wn * 8 + hl;
    int h_act = invs(q);
    int k_act = invs(kpos);
    int w = g * HH + h_act;
    float v = (k_act < INN) ? Wih[(size_t)w * INN + k_act]
                            : Whh[(size_t)w * HH + (k_act - INN)];
    g_Wc[idx] = __float2half(v);
    if (idx < HH * 4) {
        int qq = idx >> 2, gg = idx & 3;
        g_bias4[idx] = bias[gg * HH + invs(qq)];
    }
}

__global__ void prep_x_kernel(const float* __restrict__ xd) {
    size_t idx = (size_t)blockIdx.x * blockDim.x + threadIdx.x;
    if (idx >= (size_t)TT * Bsz * INN) return;
    int kpos = (int)(idx & 63);
    int b    = (int)((idx >> 6) & 1023);
    int t    = (int)(idx >> 16);
    g_x16[idx] = __float2half(xd[(size_t)b * TT * INN + (size_t)t * INN + invs(kpos)]);
}

__global__ void zero_kernel() {
    int idx = blockIdx.x * blockDim.x + threadIdx.x;
    if (idx < Bsz * HH) g_h[0][idx] = __float2half(0.0f);
    if (idx < 8) g_barr[idx] = 0;
}

__device__ __forceinline__ float sigf(float x) {
    return __fdividef(1.0f, 1.0f + __expf(-x));
}
__device__ __forceinline__ float tanhfast(float x) {
    return fmaf(2.0f, sigf(2.0f * x), -1.0f);
}

// ---------------- persistent LSTM: all 730 steps in one launch ----------------
__global__ __launch_bounds__(256, 1)
void lstm_persist_kernel() {
    extern __shared__ char smem[];
    char* Bres = smem;               // 9 chunks x 16KB resident weights
    char* Astg = smem + B_RES_B;     // 4 stages x 16KB A pipeline

    const int tid  = threadIdx.x;
    const int lane = tid & 31;
    const int wid  = tid >> 5;
    const int grp  = lane >> 2;
    const int tig  = lane & 3;
    const int wm   = wid & 1;        // 2 warps over M (64 rows each)
    const int wn   = wid >> 1;       // 4 warps over N (32 cols each)

    const int nt = blockIdx.x, mt = blockIdx.y;
    const int n0 = nt * BN, b0 = mt * BM;

    // ---- resident B load (once) ----
#pragma unroll
    for (int i = 0; i < 36; i++) {
        int u = i * 256 + tid;            // 0..9215 16B-units
        int kc  = u >> 10;
        int rem = u & 1023;
        int c = rem >> 3, cq = rem & 7;
        int fc = ((c & 1) << 2) | (c & 2);
        cpa16(Bres + kc * CHUNK_B + c * 128 + ((cq ^ fc) << 4),
              g_Wc + (size_t)(n0 + c) * KK + kc * 64 + cq * 8);
    }
    CP_COMMIT();

    const int xorb = ((grp & 1) << 6) | ((grp & 2) << 4);
    int koff[4];
#pragma unroll
    for (int ks = 0; ks < 4; ks++) koff[ks] = (ks * 32 + tig * 8) ^ xorb;

    auto load_x = [&](int t, int stage) {
        char* Ab = Astg + stage * CHUNK_B;
#pragma unroll
        for (int i = 0; i < 4; i++) {
            int u = i * 256 + tid;
            int r = u >> 3, cq = u & 7;
            int fc = ((r & 1) << 2) | (r & 2);
            cpa16(Ab + r * 128 + ((cq ^ fc) << 4),
                  g_x16 + ((size_t)t * Bsz + b0 + r) * INN + cq * 8);
        }
        CP_COMMIT();
    };
    auto load_h = [&](const __half* hp, int kc, int stage) {   // kc in 1..8
        char* Ab = Astg + stage * CHUNK_B;
#pragma unroll
        for (int i = 0; i < 4; i++) {
            int u = i * 256 + tid;
            int r = u >> 3, cq = u & 7;
            int fc = ((r & 1) << 2) | (r & 2);
            cpa16(Ab + r * 128 + ((cq ^ fc) << 4),
                  hp + ((size_t)(b0 + r) << 9) + (kc - 1) * 64 + cq * 8);
        }
        CP_COMMIT();
    };

    CP_WAIT(0);           // B resident
    __syncthreads();

    // prologue for t=0: chunk kc of step t lives in stage (t+kc)&3
    load_x(0, 0);
    load_h(g_h[0], 1, 1);
    load_h(g_h[0], 2, 2);

    const int qh = nt * 32 + wn * 8 + tig * 2;
    const float4 bg0 = *(const float4*)&g_bias4[qh * 4];
    const float4 bg1 = *(const float4*)&g_bias4[(qh + 1) * 4];

    // cell state lives in registers for the whole sequence
    float creg[4][2][2];
#pragma unroll
    for (int mf = 0; mf < 4; mf++)
#pragma unroll
        for (int rr = 0; rr < 2; rr++) {
            creg[mf][rr][0] = 0.0f;
            creg[mf][rr][1] = 0.0f;
        }

#pragma unroll 1
    for (int t = 0; t < TT; t++) {
        const __half* __restrict__ hprev = g_h[t & 1];
        __half* __restrict__ hnew = g_h[(t & 1) ^ 1];

        float acc[4][4][4];
#pragma unroll
        for (int mf = 0; mf < 4; mf++)
#pragma unroll
            for (int nf = 0; nf < 4; nf++)
#pragma unroll
                for (int r = 0; r < 4; r++) acc[mf][nf][r] = 0.0f;

#pragma unroll 1
        for (int kc = 0; kc < NCHUNK; kc++) {
            if (kc == NCHUNK - 1) CP_WAIT(1); else CP_WAIT(2);
            __syncthreads();

            if (kc + 3 < NCHUNK) {
                load_h(hprev, kc + 3, (t + kc + 3) & 3);
            } else if (kc == 6) {
                load_x(t + 1 < TT ? t + 1 : 0, (t + 9) & 3);   // cross-step x prefetch
            }

            const char* Ab = Astg + ((t + kc) & 3) * CHUNK_B;
            const char* Bb = Bres + kc * CHUNK_B;
#pragma unroll
            for (int ks = 0; ks < 4; ks++) {
                unsigned a[4][4], b[4][2];
#pragma unroll
                for (int mf = 0; mf < 4; mf++) {
                    int r0 = wm * 64 + mf * 16 + grp;
                    uint2 lo = *(const uint2*)(Ab + r0 * 128 + koff[ks]);
                    uint2 hi = *(const uint2*)(Ab + (r0 + 8) * 128 + koff[ks]);
                    a[mf][0] = lo.x; a[mf][1] = hi.x; a[mf][2] = lo.y; a[mf][3] = hi.y;
                }
#pragma unroll
                for (int nf = 0; nf < 4; nf++) {
                    int c0 = wn * 32 + nf * 8 + grp;
                    uint2 bv = *(const uint2*)(Bb + c0 * 128 + koff[ks]);
                    b[nf][0] = bv.x; b[nf][1] = bv.y;
                }
#pragma unroll
                for (int mf = 0; mf < 4; mf++)
#pragma unroll
                    for (int nf = 0; nf < 4; nf++)
                        MMA_F16(acc[mf][nf], a[mf], b[nf]);
            }
        }

        // ---- register epilogue (c resident in registers) ----
#pragma unroll
        for (int mf = 0; mf < 4; mf++) {
#pragma unroll
            for (int rr = 0; rr < 2; rr++) {
                int b = b0 + wm * 64 + mf * 16 + grp + rr * 8;
                size_t cidx = (size_t)b * HH + qh;
                float hh0, hh1;
                {
                    int j = rr * 2 + 0;
                    float zi = acc[mf][0][j] + bg0.x;
                    float zf = acc[mf][1][j] + bg0.y;
                    float zg = acc[mf][2][j] + bg0.z;
                    float zo = acc[mf][3][j] + bg0.w;
                    float cn = fmaf(sigf(zf), creg[mf][rr][0], sigf(zi) * tanhfast(zg));
                    creg[mf][rr][0] = cn;
                    hh0 = sigf(zo) * tanhfast(cn);
                }
                {
                    int j = rr * 2 + 1;
                    float zi = acc[mf][0][j] + bg1.x;
                    float zf = acc[mf][1][j] + bg1.y;
                    float zg = acc[mf][2][j] + bg1.z;
                    float zo = acc[mf][3][j] + bg1.w;
                    float cn = fmaf(sigf(zf), creg[mf][rr][1], sigf(zi) * tanhfast(zg));
                    creg[mf][rr][1] = cn;
                    hh1 = sigf(zo) * tanhfast(cn);
                }
                *(unsigned*)&hnew[cidx] = h2_as_u32(__floats2half2_rn(hh0, hh1));
            }
        }

        // ---- mt-group barrier (16 CTAs sharing this batch block) ----
        __threadfence();
        __syncthreads();
        if (tid == 0) {
            atomicAdd(&g_barr[mt], 1u);
            unsigned target = (unsigned)GROUP_CTAS * (unsigned)(t + 1);
            while (*(volatile unsigned*)&g_barr[mt] < target) { }
        }
        __syncthreads();

        // post-barrier: first h chunks of next step
        if (t + 1 < TT) {
            const __half* hp2 = g_h[(t + 1) & 1];
            load_h(hp2, 1, (t + 2) & 3);
            load_h(hp2, 2, (t + 3) & 3);
        }
    }
}

// out[b] = relu(dot(h_T[b,:], Wl) + bl)
__global__ void head_kernel(const float* __restrict__ Wl,
                            const float* __restrict__ bl,
                            float* __restrict__ out, int sel) {
    int b = blockIdx.x;
    const __half* __restrict__ h = g_h[sel] + (size_t)b * HH;
    float s = 0.0f;
    for (int i = threadIdx.x; i < HH; i += blockDim.x)
        s += __half2float(h[i]) * Wl[invs(i)];
#pragma unroll
    for (int o = 16; o; o >>= 1) s += __shfl_down_sync(0xffffffffu, s, o);
    __shared__ float red[8];
    if ((threadIdx.x & 31) == 0) red[threadIdx.x >> 5] = s;
    __syncthreads();
    if (threadIdx.x < 32) {
        s = (threadIdx.x < (blockDim.x >> 5)) ? red[threadIdx.x] : 0.0f;
#pragma unroll
        for (int o = 4; o; o >>= 1) s += __shfl_down_sync(0xffffffffu, s, o);
        if (threadIdx.x == 0) out[b] = fmaxf(s + bl[0], 0.0f);
    }
}

extern "C" void kernel_launch(void* const* d_in, const int* in_sizes, int n_in,
                              void* d_out, int out_size) {
    const float* xd   = (const float*)d_in[0];
    const float* Wih  = (const float*)d_in[1];
    const float* Whh  = (const float*)d_in[2];
    const float* bias = (const float*)d_in[3];
    const float* Wl   = (const float*)d_in[4];
    const float* bl   = (const float*)d_in[5];
    float* out = (float*)d_out;

    cudaFuncSetAttribute(lstm_persist_kernel,
                         cudaFuncAttributeMaxDynamicSharedMemorySize, SMEM_BYTES);

    prep_w_kernel<<<(G4 * KK + 255) / 256, 256>>>(Wih, Whh, bias);
    {
        size_t nx = (size_t)TT * Bsz * INN;
        prep_x_kernel<<<(unsigned)((nx + 255) / 256), 256>>>(xd);
    }
    zero_kernel<<<(Bsz * HH + 255) / 256, 256>>>();

    lstm_persist_kernel<<<dim3(G4 / BN, Bsz / BM), 256, SMEM_BYTES>>>();

    // final h in g_h[0] (t=729: (729&1)^1 = 0)
    head_kernel<<<Bsz, 256>>>(Wl, bl, out, 0);
}

// round 11
// speedup vs baseline: 7.6026x; 1.0509x over previous
#include <cuda_runtime.h>
#include <cuda_fp16.h>
#include <math.h>
#include <stdint.h>

#define Bsz 1024
#define TT  730
#define INN 64
#define HH  512
#define KK  576
#define G4  2048

#define BM 128
#define BN 128
#define NCHUNK 9
#define GROUP_CTAS 16              // CTAs per mt-group (all nt)

#define CHUNK_B 16384              // 128 rows x 128 B
#define B_RES_B (NCHUNK * CHUNK_B) // 147456: resident weights
#define A_STG_B (4 * CHUNK_B)      // 65536: 4-stage A pipeline
#define SMEM_BYTES (B_RES_B + A_STG_B)   // 212992

// ---- device-global scratch (allocation-free) ----
__device__ __half g_Wc[(size_t)G4 * KK];          // [colpos][k] fp16 (natural k)
__device__ float  g_bias4[HH * 4];                // [h][gate]
__device__ __half g_x16[(size_t)TT * Bsz * INN];  // [t][b][k] fp16 (natural)
__device__ __half g_h[2][Bsz * HH];               // hidden state (natural)
__device__ unsigned g_barr[8];                    // per-mt group barrier counters

__device__ __forceinline__ unsigned h2_as_u32(__half2 h) {
    union { __half2 h; unsigned u; } cvt;
    cvt.h = h;
    return cvt.u;
}

__device__ __forceinline__ uint32_t smem_u32(const void* p) {
    return (uint32_t)__cvta_generic_to_shared(p);
}
__device__ __forceinline__ void cpa16s(uint32_t dst, const void* src) {
    asm volatile("cp.async.cg.shared.global [%0], [%1], 16;" :: "r"(dst), "l"(src));
}
#define CP_COMMIT() asm volatile("cp.async.commit_group;")
#define CP_WAIT(n)  asm volatile("cp.async.wait_group %0;" :: "n"(n) : "memory")

#define LDSM4(r, a)                                                           \
    asm volatile("ldmatrix.sync.aligned.m8n8.x4.shared.b16 {%0,%1,%2,%3}, [%4];" \
        : "=r"((r)[0]), "=r"((r)[1]), "=r"((r)[2]), "=r"((r)[3]) : "r"(a))

#define MMA_F16(d, a, b)                                                      \
    asm volatile(                                                             \
        "mma.sync.aligned.m16n8k16.row.col.f32.f16.f16.f32 "                  \
        "{%0,%1,%2,%3}, {%4,%5,%6,%7}, {%8,%9}, {%0,%1,%2,%3};"               \
        : "+f"((d)[0]), "+f"((d)[1]), "+f"((d)[2]), "+f"((d)[3])              \
        : "r"((a)[0]), "r"((a)[1]), "r"((a)[2]), "r"((a)[3]),                 \
          "r"((b)[0]), "r"((b)[1]))

// ---------------- prep (natural layouts) ----------------
// Column position p: nt=p>>7, loc=p&127, wn=loc>>5, g=(loc>>3)&3, hl=loc&7.
// h = nt*32 + wn*8 + hl (natural). k natural.
__global__ void prep_w_kernel(const float* __restrict__ Wih,
                              const float* __restrict__ Whh,
                              const float* __restrict__ bias) {
    int idx = blockIdx.x * blockDim.x + threadIdx.x;
    if (idx >= G4 * KK) return;
    int p = idx / KK;
    int k = idx % KK;
    int nt = p >> 7, loc = p & 127;
    int wn = loc >> 5, g = (loc >> 3) & 3, hl = loc & 7;
    int h = nt * 32 + wn * 8 + hl;
    int w = g * HH + h;
    float v = (k < INN) ? Wih[(size_t)w * INN + k]
                        : Whh[(size_t)w * HH + (k - INN)];
    g_Wc[idx] = __float2half(v);
    if (idx < HH * 4) {
        int hh = idx >> 2, gg = idx & 3;
        g_bias4[idx] = bias[gg * HH + hh];
    }
}

__global__ void prep_x_kernel(const float* __restrict__ xd) {
    size_t idx = (size_t)blockIdx.x * blockDim.x + threadIdx.x;
    if (idx >= (size_t)TT * Bsz * INN) return;
    int k = (int)(idx & 63);
    int b = (int)((idx >> 6) & 1023);
    int t = (int)(idx >> 16);
    g_x16[idx] = __float2half(xd[(size_t)b * TT * INN + (size_t)t * INN + k]);
}

__global__ void zero_kernel() {
    int idx = blockIdx.x * blockDim.x + threadIdx.x;
    if (idx < Bsz * HH) g_h[0][idx] = __float2half(0.0f);
    if (idx < 8) g_barr[idx] = 0;
}

__device__ __forceinline__ float sigf(float x) {
    return __fdividef(1.0f, 1.0f + __expf(-x));
}
__device__ __forceinline__ float tanhfast(float x) {
    return fmaf(2.0f, sigf(2.0f * x), -1.0f);
}

// ---------------- persistent LSTM: all 730 steps in one launch ----------------
__global__ __launch_bounds__(256, 1)
void lstm_persist_kernel() {
    extern __shared__ char smem[];
    const uint32_t sbase = smem_u32(smem);
    const uint32_t BresS = sbase;               // 9 x 16KB resident weights
    const uint32_t AstgS = sbase + B_RES_B;     // 4 x 16KB A stages

    const int tid  = threadIdx.x;
    const int lane = tid & 31;
    const int wid  = tid >> 5;
    const int grp  = lane >> 2;
    const int tig  = lane & 3;
    const int wm   = wid & 1;        // 2 warps over M (64 rows each)
    const int wn   = wid >> 1;       // 4 warps over N (32 cols each)

    const int nt = blockIdx.x, mt = blockIdx.y;
    const int n0 = nt * BN, b0 = mt * BM;

    // ---- resident B load (once), full 3-bit XOR swizzle ----
#pragma unroll
    for (int i = 0; i < 36; i++) {
        int u = i * 256 + tid;            // 0..9215 16B-units
        int kc  = u >> 10;
        int rem = u & 1023;
        int c = rem >> 3, cq = rem & 7;
        cpa16s(BresS + kc * CHUNK_B + c * 128 + ((cq ^ (c & 7)) << 4),
               g_Wc + (size_t)(n0 + c) * KK + kc * 64 + cq * 8);
    }
    CP_COMMIT();

    // ---- per-lane ldmatrix address constants ----
    const int l7 = lane & 7;
    const uint32_t rAoff = (uint32_t)(wm * 64 + ((lane >> 3) & 1) * 8 + l7) * 128;
    const int kA = (lane >> 4) & 1;
    const uint32_t rBoff = (uint32_t)(wn * 32 + ((lane >> 4) & 1) * 8 + l7) * 128;
    const int kB = (lane >> 3) & 1;
    uint32_t swA[4], swB[4];
#pragma unroll
    for (int ks = 0; ks < 4; ks++) {
        swA[ks] = (uint32_t)(((ks * 2 + kA) ^ l7) << 4);
        swB[ks] = (uint32_t)(((ks * 2 + kB) ^ l7) << 4);
    }

    auto load_x = [&](int t, int stage) {
        uint32_t Ab = AstgS + stage * CHUNK_B;
#pragma unroll
        for (int i = 0; i < 4; i++) {
            int u = i * 256 + tid;
            int r = u >> 3, cq = u & 7;
            cpa16s(Ab + r * 128 + ((cq ^ (r & 7)) << 4),
                   g_x16 + ((size_t)t * Bsz + b0 + r) * INN + cq * 8);
        }
        CP_COMMIT();
    };
    auto load_h = [&](const __half* hp, int kc, int stage) {   // kc in 1..8
        uint32_t Ab = AstgS + stage * CHUNK_B;
#pragma unroll
        for (int i = 0; i < 4; i++) {
            int u = i * 256 + tid;
            int r = u >> 3, cq = u & 7;
            cpa16s(Ab + r * 128 + ((cq ^ (r & 7)) << 4),
                   hp + ((size_t)(b0 + r) << 9) + (kc - 1) * 64 + cq * 8);
        }
        CP_COMMIT();
    };

    CP_WAIT(0);           // B resident
    __syncthreads();

    // prologue for t=0: chunk kc of step t lives in stage (t+kc)&3
    load_x(0, 0);
    load_h(g_h[0], 1, 1);
    load_h(g_h[0], 2, 2);

    const int qh = nt * 32 + wn * 8 + tig * 2;
    const float4 bg0 = *(const float4*)&g_bias4[qh * 4];
    const float4 bg1 = *(const float4*)&g_bias4[(qh + 1) * 4];

    // cell state resident in registers for the whole sequence
    float creg[4][2][2];
#pragma unroll
    for (int mf = 0; mf < 4; mf++)
#pragma unroll
        for (int rr = 0; rr < 2; rr++) {
            creg[mf][rr][0] = 0.0f;
            creg[mf][rr][1] = 0.0f;
        }

#pragma unroll 1
    for (int t = 0; t < TT; t++) {
        const __half* __restrict__ hprev = g_h[t & 1];
        __half* __restrict__ hnew = g_h[(t & 1) ^ 1];

        float acc[4][4][4];
#pragma unroll
        for (int mf = 0; mf < 4; mf++)
#pragma unroll
            for (int nf = 0; nf < 4; nf++)
#pragma unroll
                for (int r = 0; r < 4; r++) acc[mf][nf][r] = 0.0f;

#pragma unroll 1
        for (int kc = 0; kc < NCHUNK; kc++) {
            if (kc == NCHUNK - 1) CP_WAIT(1); else CP_WAIT(2);
            __syncthreads();

            if (kc + 3 < NCHUNK) {
                load_h(hprev, kc + 3, (t + kc + 3) & 3);
            } else if (kc == 6) {
                load_x(t + 1 < TT ? t + 1 : 0, (t + 9) & 3);   // cross-step x prefetch
            }

            const uint32_t Ab = AstgS + ((t + kc) & 3) * CHUNK_B;
            const uint32_t Bb = BresS + kc * CHUNK_B;
#pragma unroll
            for (int ks = 0; ks < 4; ks++) {
                unsigned a[4][4], b[4][2];
#pragma unroll
                for (int mf = 0; mf < 4; mf++)
                    LDSM4(a[mf], Ab + rAoff + mf * 2048 + swA[ks]);
                {
                    unsigned r01[4], r23[4];
                    LDSM4(r01, Bb + rBoff + swB[ks]);           // nf 0,1
                    LDSM4(r23, Bb + rBoff + 2048 + swB[ks]);    // nf 2,3
                    b[0][0] = r01[0]; b[0][1] = r01[1];
                    b[1][0] = r01[2]; b[1][1] = r01[3];
                    b[2][0] = r23[0]; b[2][1] = r23[1];
                    b[3][0] = r23[2]; b[3][1] = r23[3];
                }
#pragma unroll
                for (int mf = 0; mf < 4; mf++)
#pragma unroll
                    for (int nf = 0; nf < 4; nf++)
                        MMA_F16(acc[mf][nf], a[mf], b[nf]);
            }
        }

        // ---- register epilogue (c resident) ----
#pragma unroll
        for (int mf = 0; mf < 4; mf++) {
#pragma unroll
            for (int rr = 0; rr < 2; rr++) {
                int b = b0 + wm * 64 + mf * 16 + grp + rr * 8;
                size_t cidx = (size_t)b * HH + qh;
                float hh0, hh1;
                {
                    int j = rr * 2 + 0;
                    float zi = acc[mf][0][j] + bg0.x;
                    float zf = acc[mf][1][j] + bg0.y;
                    float zg = acc[mf][2][j] + bg0.z;
                    float zo = acc[mf][3][j] + bg0.w;
                    float cn = fmaf(sigf(zf), creg[mf][rr][0], sigf(zi) * tanhfast(zg));
                    creg[mf][rr][0] = cn;
                    hh0 = sigf(zo) * tanhfast(cn);
                }
                {
                    int j = rr * 2 + 1;
                    float zi = acc[mf][0][j] + bg1.x;
                    float zf = acc[mf][1][j] + bg1.y;
                    float zg = acc[mf][2][j] + bg1.z;
                    float zo = acc[mf][3][j] + bg1.w;
                    float cn = fmaf(sigf(zf), creg[mf][rr][1], sigf(zi) * tanhfast(zg));
                    creg[mf][rr][1] = cn;
                    hh1 = sigf(zo) * tanhfast(cn);
                }
                *(unsigned*)&hnew[cidx] = h2_as_u32(__floats2half2_rn(hh0, hh1));
            }
        }

        // ---- mt-group barrier (16 CTAs sharing this batch block) ----
        __threadfence();
        __syncthreads();
        if (tid == 0) {
            atomicAdd(&g_barr[mt], 1u);
            unsigned target = (unsigned)GROUP_CTAS * (unsigned)(t + 1);
            while (*(volatile unsigned*)&g_barr[mt] < target) { }
        }
        __syncthreads();

        // post-barrier: first h chunks of next step
        if (t + 1 < TT) {
            const __half* hp2 = g_h[(t + 1) & 1];
            load_h(hp2, 1, (t + 2) & 3);
            load_h(hp2, 2, (t + 3) & 3);
        }
    }
}

// out[b] = relu(dot(h_T[b,:], Wl) + bl)
__global__ void head_kernel(const float* __restrict__ Wl,
                            const float* __restrict__ bl,
                            float* __restrict__ out, int sel) {
    int b = blockIdx.x;
    const __half* __restrict__ h = g_h[sel] + (size_t)b * HH;
    float s = 0.0f;
    for (int i = threadIdx.x; i < HH; i += blockDim.x)
        s += __half2float(h[i]) * Wl[i];
#pragma unroll
    for (int o = 16; o; o >>= 1) s += __shfl_down_sync(0xffffffffu, s, o);
    __shared__ float red[8];
    if ((threadIdx.x & 31) == 0) red[threadIdx.x >> 5] = s;
    __syncthreads();
    if (threadIdx.x < 32) {
        s = (threadIdx.x < (blockDim.x >> 5)) ? red[threadIdx.x] : 0.0f;
#pragma unroll
        for (int o = 4; o; o >>= 1) s += __shfl_down_sync(0xffffffffu, s, o);
        if (threadIdx.x == 0) out[b] = fmaxf(s + bl[0], 0.0f);
    }
}

extern "C" void kernel_launch(void* const* d_in, const int* in_sizes, int n_in,
                              void* d_out, int out_size) {
    const float* xd   = (const float*)d_in[0];
    const float* Wih  = (const float*)d_in[1];
    const float* Whh  = (const float*)d_in[2];
    const float* bias = (const float*)d_in[3];
    const float* Wl   = (const float*)d_in[4];
    const float* bl   = (const float*)d_in[5];
    float* out = (float*)d_out;

    cudaFuncSetAttribute(lstm_persist_kernel,
                         cudaFuncAttributeMaxDynamicSharedMemorySize, SMEM_BYTES);

    prep_w_kernel<<<(G4 * KK + 255) / 256, 256>>>(Wih, Whh, bias);
    {
        size_t nx = (size_t)TT * Bsz * INN;
        prep_x_kernel<<<(unsigned)((nx + 255) / 256), 256>>>(xd);
    }
    zero_kernel<<<(Bsz * HH + 255) / 256, 256>>>();

    lstm_persist_kernel<<<dim3(G4 / BN, Bsz / BM), 256, SMEM_BYTES>>>();

    // final h in g_h[0] (t=729: (729&1)^1 = 0)
    head_kernel<<<Bsz, 256>>>(Wl, bl, out, 0);
}

// round 12
// speedup vs baseline: 7.8722x; 1.0355x over previous
#include <cuda_runtime.h>
#include <cuda_fp16.h>
#include <math.h>
#include <stdint.h>

#define Bsz 1024
#define TT  730
#define INN 64
#define HH  512
#define KK  576
#define G4  2048

#define BM 128
#define BN 128
#define NCHUNK 9
#define GROUP_CTAS 16              // CTAs per mt-group (all nt)

#define CHUNK_B 16384              // 128 rows x 128 B
#define B_RES_B (NCHUNK * CHUNK_B) // 147456: resident weights
#define A_STG_B (4 * CHUNK_B)      // 65536: 4-stage A pipeline
#define SMEM_BYTES (B_RES_B + A_STG_B)   // 212992

// ---- device-global scratch (allocation-free) ----
__device__ __half g_Wc[(size_t)G4 * KK];          // [colpos][k] fp16
__device__ float  g_bias4[HH * 4];                // [h][gate]
__device__ __half g_x16[(size_t)TT * Bsz * INN];  // [t][b][k] fp16
__device__ __half g_h[2][Bsz * HH];               // hidden state
__device__ unsigned g_barr[8];                    // per-mt group barrier counters

__device__ __forceinline__ unsigned h2_as_u32(__half2 h) {
    union { __half2 h; unsigned u; } cvt;
    cvt.h = h;
    return cvt.u;
}
__device__ __forceinline__ uint32_t smem_u32(const void* p) {
    return (uint32_t)__cvta_generic_to_shared(p);
}
__device__ __forceinline__ void cpa16s(uint32_t dst, const void* src) {
    asm volatile("cp.async.cg.shared.global [%0], [%1], 16;" :: "r"(dst), "l"(src));
}
#define CP_COMMIT() asm volatile("cp.async.commit_group;")
#define CP_WAIT(n)  asm volatile("cp.async.wait_group %0;" :: "n"(n) : "memory")

#define LDSM4(r, a)                                                           \
    asm volatile("ldmatrix.sync.aligned.m8n8.x4.shared.b16 {%0,%1,%2,%3}, [%4];" \
        : "=r"((r)[0]), "=r"((r)[1]), "=r"((r)[2]), "=r"((r)[3]) : "r"(a))

#define MMA_F16(d, a, b)                                                      \
    asm volatile(                                                             \
        "mma.sync.aligned.m16n8k16.row.col.f32.f16.f16.f32 "                  \
        "{%0,%1,%2,%3}, {%4,%5,%6,%7}, {%8,%9}, {%0,%1,%2,%3};"               \
        : "+f"((d)[0]), "+f"((d)[1]), "+f"((d)[2]), "+f"((d)[3])              \
        : "r"((a)[0]), "r"((a)[1]), "r"((a)[2]), "r"((a)[3]),                 \
          "r"((b)[0]), "r"((b)[1]))

// ---------------- prep ----------------
__global__ void prep_w_kernel(const float* __restrict__ Wih,
                              const float* __restrict__ Whh,
                              const float* __restrict__ bias) {
    int idx = blockIdx.x * blockDim.x + threadIdx.x;
    if (idx >= G4 * KK) return;
    int p = idx / KK;
    int k = idx % KK;
    int nt = p >> 7, loc = p & 127;
    int wn = loc >> 5, g = (loc >> 3) & 3, hl = loc & 7;
    int h = nt * 32 + wn * 8 + hl;
    int w = g * HH + h;
    float v = (k < INN) ? Wih[(size_t)w * INN + k]
                        : Whh[(size_t)w * HH + (k - INN)];
    g_Wc[idx] = __float2half(v);
    if (idx < HH * 4) {
        int hh = idx >> 2, gg = idx & 3;
        g_bias4[idx] = bias[gg * HH + hh];
    }
}

__global__ void prep_x_kernel(const float* __restrict__ xd) {
    size_t idx = (size_t)blockIdx.x * blockDim.x + threadIdx.x;
    if (idx >= (size_t)TT * Bsz * INN) return;
    int k = (int)(idx & 63);
    int b = (int)((idx >> 6) & 1023);
    int t = (int)(idx >> 16);
    g_x16[idx] = __float2half(xd[(size_t)b * TT * INN + (size_t)t * INN + k]);
}

__global__ void zero_kernel() {
    int idx = blockIdx.x * blockDim.x + threadIdx.x;
    if (idx < Bsz * HH) g_h[0][idx] = __float2half(0.0f);
    if (idx < 8) g_barr[idx] = 0;
}

__device__ __forceinline__ float tanh_ap(float x) {
    float r;
    asm("tanh.approx.f32 %0, %1;" : "=f"(r) : "f"(x));
    return r;
}
__device__ __forceinline__ float sig_ap(float x) {
    return fmaf(0.5f, tanh_ap(0.5f * x), 0.5f);
}

// ---------------- persistent LSTM ----------------
__global__ __launch_bounds__(256, 1)
void lstm_persist_kernel() {
    extern __shared__ char smem[];
    const uint32_t sbase = smem_u32(smem);
    const uint32_t BresS = sbase;               // 9 x 16KB resident weights
    const uint32_t AstgS = sbase + B_RES_B;     // 4 x 16KB A stages

    const int tid  = threadIdx.x;
    const int lane = tid & 31;
    const int wid  = tid >> 5;
    const int grp  = lane >> 2;
    const int tig  = lane & 3;
    const int wm   = wid & 1;        // 2 warps over M (64 rows each)
    const int wn   = wid >> 1;       // 4 warps over N (32 cols each)

    const int nt = blockIdx.x, mt = blockIdx.y;
    const int n0 = nt * BN, b0 = mt * BM;

    // ---- resident B load (once) ----
#pragma unroll
    for (int i = 0; i < 36; i++) {
        int u = i * 256 + tid;
        int kc  = u >> 10;
        int rem = u & 1023;
        int c = rem >> 3, cq = rem & 7;
        cpa16s(BresS + kc * CHUNK_B + c * 128 + ((cq ^ (c & 7)) << 4),
               g_Wc + (size_t)(n0 + c) * KK + kc * 64 + cq * 8);
    }
    CP_COMMIT();

    // ---- per-lane ldmatrix address constants ----
    const int l7 = lane & 7;
    const uint32_t rAoff = (uint32_t)(wm * 64 + ((lane >> 3) & 1) * 8 + l7) * 128;
    const int kA = (lane >> 4) & 1;
    const uint32_t rBoff = (uint32_t)(wn * 32 + ((lane >> 4) & 1) * 8 + l7) * 128;
    const int kB = (lane >> 3) & 1;
    uint32_t swA[4], swB[4];
#pragma unroll
    for (int ks = 0; ks < 4; ks++) {
        swA[ks] = (uint32_t)(((ks * 2 + kA) ^ l7) << 4);
        swB[ks] = (uint32_t)(((ks * 2 + kB) ^ l7) << 4);
    }

    auto load_x = [&](int t, int stage) {
        uint32_t Ab = AstgS + stage * CHUNK_B;
#pragma unroll
        for (int i = 0; i < 4; i++) {
            int u = i * 256 + tid;
            int r = u >> 3, cq = u & 7;
            cpa16s(Ab + r * 128 + ((cq ^ (r & 7)) << 4),
                   g_x16 + ((size_t)t * Bsz + b0 + r) * INN + cq * 8);
        }
        CP_COMMIT();
    };
    auto load_h = [&](const __half* hp, int kc, int stage) {   // kc in 1..8
        uint32_t Ab = AstgS + stage * CHUNK_B;
#pragma unroll
        for (int i = 0; i < 4; i++) {
            int u = i * 256 + tid;
            int r = u >> 3, cq = u & 7;
            cpa16s(Ab + r * 128 + ((cq ^ (r & 7)) << 4),
                   hp + ((size_t)(b0 + r) << 9) + (kc - 1) * 64 + cq * 8);
        }
        CP_COMMIT();
    };

    // slice fragment loader (A + B of k16 slice ks)
    auto ldsm_slice = [&](uint32_t Ab, uint32_t Bb, int ks,
                          unsigned (*a)[4], unsigned (*b)[2]) {
#pragma unroll
        for (int mf = 0; mf < 4; mf++)
            LDSM4(a[mf], Ab + rAoff + mf * 2048 + swA[ks]);
        unsigned r01[4], r23[4];
        LDSM4(r01, Bb + rBoff + swB[ks]);
        LDSM4(r23, Bb + rBoff + 2048 + swB[ks]);
        b[0][0] = r01[0]; b[0][1] = r01[1];
        b[1][0] = r01[2]; b[1][1] = r01[3];
        b[2][0] = r23[0]; b[2][1] = r23[1];
        b[3][0] = r23[2]; b[3][1] = r23[3];
    };

    CP_WAIT(0);           // B resident
    __syncthreads();

    load_x(0, 0);
    load_h(g_h[0], 1, 1);
    load_h(g_h[0], 2, 2);

    const int qh = nt * 32 + wn * 8 + tig * 2;
    const float4 bg0 = *(const float4*)&g_bias4[qh * 4];
    const float4 bg1 = *(const float4*)&g_bias4[(qh + 1) * 4];

    float creg[4][2][2];
#pragma unroll
    for (int mf = 0; mf < 4; mf++)
#pragma unroll
        for (int rr = 0; rr < 2; rr++) {
            creg[mf][rr][0] = 0.0f;
            creg[mf][rr][1] = 0.0f;
        }

#pragma unroll 1
    for (int t = 0; t < TT; t++) {
        const __half* __restrict__ hprev = g_h[t & 1];
        __half* __restrict__ hnew = g_h[(t & 1) ^ 1];

        float acc[4][4][4];
#pragma unroll
        for (int mf = 0; mf < 4; mf++)
#pragma unroll
            for (int nf = 0; nf < 4; nf++)
#pragma unroll
                for (int r = 0; r < 4; r++) acc[mf][nf][r] = 0.0f;

#pragma unroll 1
        for (int kc = 0; kc < NCHUNK; kc++) {
            if (kc == NCHUNK - 1) CP_WAIT(1); else CP_WAIT(2);
            __syncthreads();

            if (kc + 3 < NCHUNK) {
                load_h(hprev, kc + 3, (t + kc + 3) & 3);
            } else if (kc == 6) {
                load_x(t + 1 < TT ? t + 1 : 0, (t + 9) & 3);
            }

            const uint32_t Ab = AstgS + ((t + kc) & 3) * CHUNK_B;
            const uint32_t Bb = BresS + kc * CHUNK_B;

            // register double-buffered fragment pipeline
            unsigned afrag[2][4][4], bfrag[2][4][2];
            ldsm_slice(Ab, Bb, 0, afrag[0], bfrag[0]);
#pragma unroll
            for (int ks = 0; ks < 4; ks++) {
                const int cur = ks & 1;
                if (ks < 3)
                    ldsm_slice(Ab, Bb, ks + 1, afrag[cur ^ 1], bfrag[cur ^ 1]);
#pragma unroll
                for (int mf = 0; mf < 4; mf++)
#pragma unroll
                    for (int nf = 0; nf < 4; nf++)
                        MMA_F16(acc[mf][nf], afrag[cur][mf], bfrag[cur][nf]);
            }
        }

        // ---- register epilogue (c resident, tanh.approx gates) ----
#pragma unroll
        for (int mf = 0; mf < 4; mf++) {
#pragma unroll
            for (int rr = 0; rr < 2; rr++) {
                int b = b0 + wm * 64 + mf * 16 + grp + rr * 8;
                size_t cidx = (size_t)b * HH + qh;
                float hh0, hh1;
                {
                    int j = rr * 2 + 0;
                    float zi = acc[mf][0][j] + bg0.x;
                    float zf = acc[mf][1][j] + bg0.y;
                    float zg = acc[mf][2][j] + bg0.z;
                    float zo = acc[mf][3][j] + bg0.w;
                    float cn = fmaf(sig_ap(zf), creg[mf][rr][0], sig_ap(zi) * tanh_ap(zg));
                    creg[mf][rr][0] = cn;
                    hh0 = sig_ap(zo) * tanh_ap(cn);
                }
                {
                    int j = rr * 2 + 1;
                    float zi = acc[mf][0][j] + bg1.x;
                    float zf = acc[mf][1][j] + bg1.y;
                    float zg = acc[mf][2][j] + bg1.z;
                    float zo = acc[mf][3][j] + bg1.w;
                    float cn = fmaf(sig_ap(zf), creg[mf][rr][1], sig_ap(zi) * tanh_ap(zg));
                    creg[mf][rr][1] = cn;
                    hh1 = sig_ap(zo) * tanh_ap(cn);
                }
                *(unsigned*)&hnew[cidx] = h2_as_u32(__floats2half2_rn(hh0, hh1));
            }
        }

        // ---- mt-group barrier ----
        __threadfence();
        __syncthreads();
        if (tid == 0) {
            atomicAdd(&g_barr[mt], 1u);
            unsigned target = (unsigned)GROUP_CTAS * (unsigned)(t + 1);
            while (*(volatile unsigned*)&g_barr[mt] < target) { }
        }
        __syncthreads();

        if (t + 1 < TT) {
            const __half* hp2 = g_h[(t + 1) & 1];
            load_h(hp2, 1, (t + 2) & 3);
            load_h(hp2, 2, (t + 3) & 3);
        }
    }
}

// out[b] = relu(dot(h_T[b,:], Wl) + bl)
__global__ void head_kernel(const float* __restrict__ Wl,
                            const float* __restrict__ bl,
                            float* __restrict__ out, int sel) {
    int b = blockIdx.x;
    const __half* __restrict__ h = g_h[sel] + (size_t)b * HH;
    float s = 0.0f;
    for (int i = threadIdx.x; i < HH; i += blockDim.x)
        s += __half2float(h[i]) * Wl[i];
#pragma unroll
    for (int o = 16; o; o >>= 1) s += __shfl_down_sync(0xffffffffu, s, o);
    __shared__ float red[8];
    if ((threadIdx.x & 31) == 0) red[threadIdx.x >> 5] = s;
    __syncthreads();
    if (threadIdx.x < 32) {
        s = (threadIdx.x < (blockDim.x >> 5)) ? red[threadIdx.x] : 0.0f;
#pragma unroll
        for (int o = 4; o; o >>= 1) s += __shfl_down_sync(0xffffffffu, s, o);
        if (threadIdx.x == 0) out[b] = fmaxf(s + bl[0], 0.0f);
    }
}

extern "C" void kernel_launch(void* const* d_in, const int* in_sizes, int n_in,
                              void* d_out, int out_size) {
    const float* xd   = (const float*)d_in[0];
    const float* Wih  = (const float*)d_in[1];
    const float* Whh  = (const float*)d_in[2];
    const float* bias = (const float*)d_in[3];
    const float* Wl   = (const float*)d_in[4];
    const float* bl   = (const float*)d_in[5];
    float* out = (float*)d_out;

    cudaFuncSetAttribute(lstm_persist_kernel,
                         cudaFuncAttributeMaxDynamicSharedMemorySize, SMEM_BYTES);

    prep_w_kernel<<<(G4 * KK + 255) / 256, 256>>>(Wih, Whh, bias);
    {
        size_t nx = (size_t)TT * Bsz * INN;
        prep_x_kernel<<<(unsigned)((nx + 255) / 256), 256>>>(xd);
    }
    zero_kernel<<<(Bsz * HH + 255) / 256, 256>>>();

    lstm_persist_kernel<<<dim3(G4 / BN, Bsz / BM), 256, SMEM_BYTES>>>();

    head_kernel<<<Bsz, 256>>>(Wl, bl, out, 0);
}

// round 13
// speedup vs baseline: 8.4037x; 1.0675x over previous
#include <cuda_runtime.h>
#include <cuda_fp16.h>
#include <math.h>
#include <stdint.h>

#define Bsz 1024
#define TT  730
#define INN 64
#define HH  512
#define KK  576
#define G4  2048

#define BM 128
#define BN 128
#define NCHUNK 9
#define GROUP_CTAS 16              // CTAs per mt-group (all nt)

#define CHUNK_B 16384              // 128 rows x 128 B
#define B_RES_B (NCHUNK * CHUNK_B) // 147456: resident weights
#define A_STG_B (4 * CHUNK_B)      // 65536: 4-stage A pipeline
#define SMEM_BYTES (B_RES_B + A_STG_B)   // 212992

// ---- device-global scratch (allocation-free) ----
__device__ __half g_Wc[(size_t)G4 * KK];          // [colpos][k] fp16
__device__ float  g_bias4[HH * 4];                // [h][gate]
__device__ __half g_x16[(size_t)TT * Bsz * INN];  // [t][b][k] fp16
__device__ __half g_h[2][Bsz * HH];               // hidden state
__device__ unsigned g_barr[8];                    // per-mt group barrier counters

__device__ __forceinline__ unsigned h2_as_u32(__half2 h) {
    union { __half2 h; unsigned u; } cvt;
    cvt.h = h;
    return cvt.u;
}
__device__ __forceinline__ uint32_t smem_u32(const void* p) {
    return (uint32_t)__cvta_generic_to_shared(p);
}
__device__ __forceinline__ void cpa16s(uint32_t dst, const void* src) {
    asm volatile("cp.async.cg.shared.global [%0], [%1], 16;" :: "r"(dst), "l"(src));
}
#define CP_COMMIT() asm volatile("cp.async.commit_group;")
#define CP_WAIT(n)  asm volatile("cp.async.wait_group %0;" :: "n"(n) : "memory")

#define LDSM4(r, a)                                                           \
    asm volatile("ldmatrix.sync.aligned.m8n8.x4.shared.b16 {%0,%1,%2,%3}, [%4];" \
        : "=r"((r)[0]), "=r"((r)[1]), "=r"((r)[2]), "=r"((r)[3]) : "r"(a))

#define MMA_F16(d, a, b)                                                      \
    asm volatile(                                                             \
        "mma.sync.aligned.m16n8k16.row.col.f32.f16.f16.f32 "                  \
        "{%0,%1,%2,%3}, {%4,%5,%6,%7}, {%8,%9}, {%0,%1,%2,%3};"               \
        : "+f"((d)[0]), "+f"((d)[1]), "+f"((d)[2]), "+f"((d)[3])              \
        : "r"((a)[0]), "r"((a)[1]), "r"((a)[2]), "r"((a)[3]),                 \
          "r"((b)[0]), "r"((b)[1]))

// ---------------- prep ----------------
__global__ void prep_w_kernel(const float* __restrict__ Wih,
                              const float* __restrict__ Whh,
                              const float* __restrict__ bias) {
    int idx = blockIdx.x * blockDim.x + threadIdx.x;
    if (idx >= G4 * KK) return;
    int p = idx / KK;
    int k = idx % KK;
    int nt = p >> 7, loc = p & 127;
    int wn = loc >> 5, g = (loc >> 3) & 3, hl = loc & 7;
    int h = nt * 32 + wn * 8 + hl;
    int w = g * HH + h;
    float v = (k < INN) ? Wih[(size_t)w * INN + k]
                        : Whh[(size_t)w * HH + (k - INN)];
    g_Wc[idx] = __float2half(v);
    if (idx < HH * 4) {
        int hh = idx >> 2, gg = idx & 3;
        g_bias4[idx] = bias[gg * HH + hh];
    }
}

__global__ void prep_x_kernel(const float* __restrict__ xd) {
    size_t idx = (size_t)blockIdx.x * blockDim.x + threadIdx.x;
    if (idx >= (size_t)TT * Bsz * INN) return;
    int k = (int)(idx & 63);
    int b = (int)((idx >> 6) & 1023);
    int t = (int)(idx >> 16);
    g_x16[idx] = __float2half(xd[(size_t)b * TT * INN + (size_t)t * INN + k]);
}

__global__ void zero_kernel() {
    int idx = blockIdx.x * blockDim.x + threadIdx.x;
    if (idx < Bsz * HH) g_h[0][idx] = __float2half(0.0f);
    if (idx < 8) g_barr[idx] = 0;
}

__device__ __forceinline__ float tanh_ap(float x) {
    float r;
    asm("tanh.approx.f32 %0, %1;" : "=f"(r) : "f"(x));
    return r;
}
__device__ __forceinline__ float sig_ap(float x) {
    return fmaf(0.5f, tanh_ap(0.5f * x), 0.5f);
}

// ---------------- persistent LSTM ----------------
__global__ __launch_bounds__(256, 1)
void lstm_persist_kernel() {
    extern __shared__ char smem[];
    const uint32_t sbase = smem_u32(smem);
    const uint32_t BresS = sbase;               // 9 x 16KB resident weights
    const uint32_t AstgS = sbase + B_RES_B;     // 4 x 16KB A stages

    const int tid  = threadIdx.x;
    const int lane = tid & 31;
    const int wid  = tid >> 5;
    const int grp  = lane >> 2;
    const int tig  = lane & 3;
    const int wm   = wid & 1;        // 2 warps over M (64 rows each)
    const int wn   = wid >> 1;       // 4 warps over N (32 cols each)

    const int nt = blockIdx.x, mt = blockIdx.y;
    const int n0 = nt * BN, b0 = mt * BM;

    // ---- resident B load (once) ----
#pragma unroll
    for (int i = 0; i < 36; i++) {
        int u = i * 256 + tid;
        int kc  = u >> 10;
        int rem = u & 1023;
        int c = rem >> 3, cq = rem & 7;
        cpa16s(BresS + kc * CHUNK_B + c * 128 + ((cq ^ (c & 7)) << 4),
               g_Wc + (size_t)(n0 + c) * KK + kc * 64 + cq * 8);
    }
    CP_COMMIT();

    // ---- per-lane ldmatrix address constants ----
    const int l7 = lane & 7;
    const uint32_t rAoff = (uint32_t)(wm * 64 + ((lane >> 3) & 1) * 8 + l7) * 128;
    const int kA = (lane >> 4) & 1;
    const uint32_t rBoff = (uint32_t)(wn * 32 + ((lane >> 4) & 1) * 8 + l7) * 128;
    const int kB = (lane >> 3) & 1;
    uint32_t swA[4], swB[4];
#pragma unroll
    for (int ks = 0; ks < 4; ks++) {
        swA[ks] = (uint32_t)(((ks * 2 + kA) ^ l7) << 4);
        swB[ks] = (uint32_t)(((ks * 2 + kB) ^ l7) << 4);
    }

    auto load_x = [&](int t, int stage) {
        uint32_t Ab = AstgS + stage * CHUNK_B;
#pragma unroll
        for (int i = 0; i < 4; i++) {
            int u = i * 256 + tid;
            int r = u >> 3, cq = u & 7;
            cpa16s(Ab + r * 128 + ((cq ^ (r & 7)) << 4),
                   g_x16 + ((size_t)t * Bsz + b0 + r) * INN + cq * 8);
        }
        CP_COMMIT();
    };
    auto load_h = [&](const __half* hp, int kc, int stage) {   // kc in 1..8
        uint32_t Ab = AstgS + stage * CHUNK_B;
#pragma unroll
        for (int i = 0; i < 4; i++) {
            int u = i * 256 + tid;
            int r = u >> 3, cq = u & 7;
            cpa16s(Ab + r * 128 + ((cq ^ (r & 7)) << 4),
                   hp + ((size_t)(b0 + r) << 9) + (kc - 1) * 64 + cq * 8);
        }
        CP_COMMIT();
    };

    // fragment slice loader (A + B of k16 slice ks)
    auto ldsm_slice = [&](uint32_t Ab, uint32_t Bb, int ks,
                          unsigned (*a)[4], unsigned (*b)[2]) {
#pragma unroll
        for (int mf = 0; mf < 4; mf++)
            LDSM4(a[mf], Ab + rAoff + mf * 2048 + swA[ks]);
        unsigned r01[4], r23[4];
        LDSM4(r01, Bb + rBoff + swB[ks]);
        LDSM4(r23, Bb + rBoff + 2048 + swB[ks]);
        b[0][0] = r01[0]; b[0][1] = r01[1];
        b[1][0] = r01[2]; b[1][1] = r01[3];
        b[2][0] = r23[0]; b[2][1] = r23[1];
        b[3][0] = r23[2]; b[3][1] = r23[3];
    };

    // prologue (t=0): x0 -> stage0, h1 -> stage1, h2 -> stage2
    load_x(0, 0);
    load_h(g_h[0], 1, 1);
    load_h(g_h[0], 2, 2);
    CP_WAIT(2);            // B resident + x0 complete
    __syncthreads();

    unsigned f0a[4][4], f0b[4][2], f1a[4][4], f1b[4][2];
    ldsm_slice(AstgS + 0 * CHUNK_B, BresS + 0 * CHUNK_B, 0, f0a, f0b);  // chunk0 slice0

    const int qh = nt * 32 + wn * 8 + tig * 2;
    const float4 bg0 = *(const float4*)&g_bias4[qh * 4];
    const float4 bg1 = *(const float4*)&g_bias4[(qh + 1) * 4];

    float creg[4][2][2];
#pragma unroll
    for (int mf = 0; mf < 4; mf++)
#pragma unroll
        for (int rr = 0; rr < 2; rr++) {
            creg[mf][rr][0] = 0.0f;
            creg[mf][rr][1] = 0.0f;
        }

#pragma unroll 1
    for (int t = 0; t < TT; t++) {
        const __half* __restrict__ hprev = g_h[t & 1];
        __half* __restrict__ hnew = g_h[(t & 1) ^ 1];

        float acc[4][4][4];
#pragma unroll
        for (int mf = 0; mf < 4; mf++)
#pragma unroll
            for (int nf = 0; nf < 4; nf++)
#pragma unroll
                for (int r = 0; r < 4; r++) acc[mf][nf][r] = 0.0f;

#pragma unroll 1
        for (int kc = 0; kc < NCHUNK; kc++) {
            // top: issue next A loads (stage kc+3) / cross-step x prefetch
            if (kc < 6) {
                load_h(hprev, kc + 3, (t + kc + 3) & 3);
            } else if (kc == 6) {
                load_x(t + 1 < TT ? t + 1 : 0, (t + 9) & 3);
            }

            const uint32_t Ab = AstgS + ((t + kc) & 3) * CHUNK_B;
            const uint32_t Bb = BresS + kc * CHUNK_B;

            // f0 holds slice0 of this chunk (prefetched at previous tail)
            ldsm_slice(Ab, Bb, 1, f1a, f1b);
#pragma unroll
            for (int mf = 0; mf < 4; mf++)
#pragma unroll
                for (int nf = 0; nf < 4; nf++)
                    MMA_F16(acc[mf][nf], f0a[mf], f0b[nf]);
            ldsm_slice(Ab, Bb, 2, f0a, f0b);
#pragma unroll
            for (int mf = 0; mf < 4; mf++)
#pragma unroll
                for (int nf = 0; nf < 4; nf++)
                    MMA_F16(acc[mf][nf], f1a[mf], f1b[nf]);
            ldsm_slice(Ab, Bb, 3, f1a, f1b);
#pragma unroll
            for (int mf = 0; mf < 4; mf++)
#pragma unroll
                for (int nf = 0; nf < 4; nf++)
                    MMA_F16(acc[mf][nf], f0a[mf], f0b[nf]);

            // tail: sync for next stage, prefetch next chunk slice0, then slice3 MMAs
            if (kc < 8) {
                if (kc == 7) CP_WAIT(1); else CP_WAIT(2);
                __syncthreads();
                ldsm_slice(AstgS + ((t + kc + 1) & 3) * CHUNK_B,
                           BresS + (kc + 1) * CHUNK_B, 0, f0a, f0b);
            } else {
                CP_WAIT(0);          // x stage for next step complete
                __syncthreads();
                ldsm_slice(AstgS + ((t + 1) & 3) * CHUNK_B,
                           BresS + 0 * CHUNK_B, 0, f0a, f0b);
            }
#pragma unroll
            for (int mf = 0; mf < 4; mf++)
#pragma unroll
                for (int nf = 0; nf < 4; nf++)
                    MMA_F16(acc[mf][nf], f1a[mf], f1b[nf]);
        }

        // ---- register epilogue (c resident, tanh.approx gates) ----
#pragma unroll
        for (int mf = 0; mf < 4; mf++) {
#pragma unroll
            for (int rr = 0; rr < 2; rr++) {
                int b = b0 + wm * 64 + mf * 16 + grp + rr * 8;
                size_t cidx = (size_t)b * HH + qh;
                float hh0, hh1;
                {
                    int j = rr * 2 + 0;
                    float zi = acc[mf][0][j] + bg0.x;
                    float zf = acc[mf][1][j] + bg0.y;
                    float zg = acc[mf][2][j] + bg0.z;
                    float zo = acc[mf][3][j] + bg0.w;
                    float cn = fmaf(sig_ap(zf), creg[mf][rr][0], sig_ap(zi) * tanh_ap(zg));
                    creg[mf][rr][0] = cn;
                    hh0 = sig_ap(zo) * tanh_ap(cn);
                }
                {
                    int j = rr * 2 + 1;
                    float zi = acc[mf][0][j] + bg1.x;
                    float zf = acc[mf][1][j] + bg1.y;
                    float zg = acc[mf][2][j] + bg1.z;
                    float zo = acc[mf][3][j] + bg1.w;
                    float cn = fmaf(sig_ap(zf), creg[mf][rr][1], sig_ap(zi) * tanh_ap(zg));
                    creg[mf][rr][1] = cn;
                    hh1 = sig_ap(zo) * tanh_ap(cn);
                }
                *(unsigned*)&hnew[cidx] = h2_as_u32(__floats2half2_rn(hh0, hh1));
            }
        }

        // ---- mt-group barrier ----
        __threadfence();
        __syncthreads();
        if (tid == 0) {
            atomicAdd(&g_barr[mt], 1u);
            unsigned target = (unsigned)GROUP_CTAS * (unsigned)(t + 1);
            while (*(volatile unsigned*)&g_barr[mt] < target) { }
        }
        __syncthreads();

        if (t + 1 < TT) {
            const __half* hp2 = g_h[(t + 1) & 1];
            load_h(hp2, 1, (t + 2) & 3);
            load_h(hp2, 2, (t + 3) & 3);
        }
    }
}

// out[b] = relu(dot(h_T[b,:], Wl) + bl)
__global__ void head_kernel(const float* __restrict__ Wl,
                            const float* __restrict__ bl,
                            float* __restrict__ out, int sel) {
    int b = blockIdx.x;
    const __half* __restrict__ h = g_h[sel] + (size_t)b * HH;
    float s = 0.0f;
    for (int i = threadIdx.x; i < HH; i += blockDim.x)
        s += __half2float(h[i]) * Wl[i];
#pragma unroll
    for (int o = 16; o; o >>= 1) s += __shfl_down_sync(0xffffffffu, s, o);
    __shared__ float red[8];
    if ((threadIdx.x & 31) == 0) red[threadIdx.x >> 5] = s;
    __syncthreads();
    if (threadIdx.x < 32) {
        s = (threadIdx.x < (blockDim.x >> 5)) ? red[threadIdx.x] : 0.0f;
#pragma unroll
        for (int o = 4; o; o >>= 1) s += __shfl_down_sync(0xffffffffu, s, o);
        if (threadIdx.x == 0) out[b] = fmaxf(s + bl[0], 0.0f);
    }
}

extern "C" void kernel_launch(void* const* d_in, const int* in_sizes, int n_in,
                              void* d_out, int out_size) {
    const float* xd   = (const float*)d_in[0];
    const float* Wih  = (const float*)d_in[1];
    const float* Whh  = (const float*)d_in[2];
    const float* bias = (const float*)d_in[3];
    const float* Wl   = (const float*)d_in[4];
    const float* bl   = (const float*)d_in[5];
    float* out = (float*)d_out;

    cudaFuncSetAttribute(lstm_persist_kernel,
                         cudaFuncAttributeMaxDynamicSharedMemorySize, SMEM_BYTES);

    prep_w_kernel<<<(G4 * KK + 255) / 256, 256>>>(Wih, Whh, bias);
    {
        size_t nx = (size_t)TT * Bsz * INN;
        prep_x_kernel<<<(unsigned)((nx + 255) / 256), 256>>>(xd);
    }
    zero_kernel<<<(Bsz * HH + 255) / 256, 256>>>();

    lstm_persist_kernel<<<dim3(G4 / BN, Bsz / BM), 256, SMEM_BYTES>>>();

    head_kernel<<<Bsz, 256>>>(Wl, bl, out, 0);
}